// round 6
// baseline (speedup 1.0000x reference)
#include <cuda_runtime.h>
#include <cuda_bf16.h>
#include <math.h>
#include <stdint.h>

// Problem constants
#define BB 2
#define QQ 4096
#define CC 64
#define HH 64
#define WW 64
#define CK 576          // C*9
#define KIN 580         // CK + 4
#define KINP 608        // padded to multiple of 32
#define HID 256
#define NROW (BB*QQ)        // 8192
#define NROW4 (BB*QQ*4)     // 32768

// ---------------- scratch (device globals; no allocation) ----------------
__device__ float g_INP[NROW4 * KINP];     // [32768, 608] tf32-rounded
__device__ float g_QRY[NROW * CK];        // [8192, 576] fp32
__device__ float g_H  [NROW4 * 512];      // [32768, 512]: cols 0..255 Hk, 256..511 Hv
__device__ float g_PK [NROW4 * CK];       // fp32
__device__ float g_PV [NROW4 * CK];
__device__ float g_X  [NROW * CK];        // tf32-rounded
__device__ float g_Hq [NROW * HID];
// weights (tf32-rounded), [N, K] K-major
__device__ float g_W1t [512 * KINP];      // kW1t rows 0..255, vW1t rows 256..511
__device__ float g_b1  [512];
__device__ float g_kW2t[CK * HID];
__device__ float g_vW2t[CK * HID];
__device__ float g_qW1t[HID * CK];

__device__ __forceinline__ float tf32r(float x) {
    uint32_t y;
    asm("cvt.rna.tf32.f32 %0, %1;" : "=r"(y) : "f"(x));
    return __uint_as_float(y);
}
__device__ __forceinline__ uint32_t s2u(const void* p) {
    uint32_t a;
    asm("{ .reg .u64 t; cvta.to.shared.u64 t, %1; cvt.u32.u64 %0, t; }" : "=r"(a) : "l"(p));
    return a;
}

// ---------------- weight transpose / pad / tf32 round ----------------------
__global__ void prep_weights(const float* __restrict__ kW1, const float* __restrict__ vW1,
                             const float* __restrict__ kW2, const float* __restrict__ vW2,
                             const float* __restrict__ qW1,
                             const float* __restrict__ kb1, const float* __restrict__ vb1) {
    int i = blockIdx.x * 256 + threadIdx.x;
    if (i < 512 * KINP) {           // fused W1: [512, 608]
        int n = i / KINP, k = i - n * KINP;
        float v = 0.f;
        if (k < KIN) v = (n < HID) ? kW1[k * HID + n] : vW1[k * HID + (n - HID)];
        g_W1t[i] = tf32r(v);
    }
    if (i < CK * HID) {             // [576, 256] from [256, 576]
        int n = i / HID, k = i - n * HID;
        g_kW2t[i] = tf32r(kW2[k * CK + n]);
        g_vW2t[i] = tf32r(vW2[k * CK + n]);
    }
    if (i < HID * CK) {             // [256, 576] from [576, 256]
        int n = i / CK, k = i - n * CK;
        g_qW1t[i] = tf32r(qW1[k * HID + n]);
    }
    if (i < 512)
        g_b1[i] = (i < HID) ? kb1[i] : vb1[i - HID];
}

// ---------------- setup: gather unfold samples, build INP + query ----------
__device__ __forceinline__ int nearest_idx(float c) {
    float f = ((c + 1.0f) * 64.0f - 1.0f) * 0.5f + 0.5f;
    int i = (int)floorf(f);
    return i < 0 ? 0 : (i > 63 ? 63 : i);
}

__global__ __launch_bounds__(128) void setup_kernel(
    const float* __restrict__ feature, const float* __restrict__ coord,
    const float* __restrict__ scale) {
    const int bq = blockIdx.x;
    const int b  = bq >> 12;
    const int tid = threadIdx.x;

    const float cy = coord[bq * 2 + 0];
    const float cx = coord[bq * 2 + 1];
    const float s0 = scale[bq * 2 + 0];
    const float s1 = scale[bq * 2 + 1];
    const float lo = -1.0f + 1e-6f, hi = 1.0f - 1e-6f;

    int   qy[4], qx[4];
    float area[4];
    const float rx = 1.0f / 64.0f, ry = 1.0f / 64.0f;
    #pragma unroll
    for (int s = 0; s < 4; s++) {
        float vx = (s >= 2) ? 1.0f : -1.0f;
        float vy = (s & 1)  ? 1.0f : -1.0f;
        float c0 = fminf(fmaxf(cy + vx * rx + 1e-6f, lo), hi);
        float c1 = fminf(fmaxf(cx + vy * ry + 1e-6f, lo), hi);
        int iy = nearest_idx(c0), ix = nearest_idx(c1);
        qy[s] = iy; qx[s] = ix;
        float qc0 = -1.0f + (2.0f * iy + 1.0f) / 64.0f;
        float qc1 = -1.0f + (2.0f * ix + 1.0f) / 64.0f;
        area[s] = fabsf((cy - qc0) * 64.0f * (cx - qc1) * 64.0f) + 1e-9f;
    }
    float tot = area[0] + area[1] + area[2] + area[3];
    float qw[4];
    #pragma unroll
    for (int s = 0; s < 4; s++) qw[s] = area[3 - s] / tot;

    const float sc00 = scale[(b * QQ) * 2 + 0];
    const float sc01 = scale[(b * QQ) * 2 + 1];
    const float invtx = (1.0f - sc00) / 63.0f;
    const float invty = (1.0f - sc01) / 63.0f;
    int   ky[4], kx[4];
    float kr0[4], kr1[4];
    #pragma unroll
    for (int s = 0; s < 4; s++) {
        float vx = (s >= 2) ? 1.0f : -1.0f;
        float vy = (s & 1)  ? 1.0f : -1.0f;
        float c0 = fminf(fmaxf(cy + vx * invtx + 1e-6f, lo), hi);
        float c1 = fminf(fmaxf(cx + vy * invty + 1e-6f, lo), hi);
        int iy = nearest_idx(c0), ix = nearest_idx(c1);
        ky[s] = iy; kx[s] = ix;
        float qc0 = -1.0f + (2.0f * iy + 1.0f) / 64.0f;
        float qc1 = -1.0f + (2.0f * ix + 1.0f) / 64.0f;
        kr0[s] = (cy - qc0) * 64.0f;
        kr1[s] = (cx - qc1) * 64.0f;
    }

    const float* fb = feature + (size_t)b * CC * HH * WW;
    for (int k = tid; k < CK; k += 128) {
        int c = k / 9, p = k - c * 9;
        int di = p / 3 - 1, dj = p - (p / 3) * 3 - 1;
        const float* fc = fb + (size_t)c * (HH * WW);
        float qacc = 0.f;
        #pragma unroll
        for (int s = 0; s < 4; s++) {
            int y = qy[s] + di, x = qx[s] + dj;
            float v = ((unsigned)y < 64u && (unsigned)x < 64u) ? fc[y * 64 + x] : 0.f;
            qacc += qw[s] * v;
        }
        g_QRY[(size_t)bq * CK + k] = qacc;
        #pragma unroll
        for (int s = 0; s < 4; s++) {
            int y = ky[s] + di, x = kx[s] + dj;
            float v = ((unsigned)y < 64u && (unsigned)x < 64u) ? fc[y * 64 + x] : 0.f;
            g_INP[((size_t)(bq * 4 + s)) * KINP + k] = tf32r(v);
        }
    }
    {   // cols 576..607: rel(2), scale(2), zeros. 128 thr = 4 shifts x 32 cols.
        int s = tid >> 5, cc = tid & 31;
        float v = 0.f;
        if (cc == 0) v = kr0[s];
        else if (cc == 1) v = kr1[s];
        else if (cc == 2) v = s0 * 64.0f;
        else if (cc == 3) v = s1 * 64.0f;
        g_INP[((size_t)(bq * 4 + s)) * KINP + 576 + cc] = tf32r(v);
    }
}

// ---------------- mma.sync tf32 GEMM (v4 fragment loads) --------------------
// C[M,N] = A[M,K(lda)] @ B[N,K]^T.  BM=128, BN=128, BK=32, 2-stage cp.async.
// Fragment k-slot remap: lane tg holds k=4tg..4tg+3 via one LDS.128, split
// across two k8 MMAs. A and B use the identical remap -> result exact.
// PS=48: conflict-free v4 LDS + STS.128.
// EPI 0: tf32r(relu(acc+bias)).  EPI 1: (acc+bias)*mul[gm*ldmul+gn].
#define PS 48
#define TILEF (128*PS)             // 6144 floats per operand buffer
#define STAGEF (2*TILEF)           // 12288 floats per stage
#define SMEMB (2*STAGEF*4)         // 98304 bytes

__device__ __forceinline__ void cp16(uint32_t dst, const float* src) {
    asm volatile("cp.async.cg.shared.global [%0], [%1], 16;" :: "r"(dst), "l"(src) : "memory");
}
__device__ __forceinline__ void cp16p(uint32_t dst, const float* src, int sz) {
    asm volatile("cp.async.cg.shared.global [%0], [%1], 16, %2;" :: "r"(dst), "l"(src), "r"(sz) : "memory");
}
#define MMA_TF32(acc, a0, a1, a2, a3, b0, b1)                                    \
    asm volatile("mma.sync.aligned.m16n8k8.row.col.f32.tf32.tf32.f32 "           \
        "{%0,%1,%2,%3}, {%4,%5,%6,%7}, {%8,%9}, {%0,%1,%2,%3};"                  \
        : "+f"((acc)[0]), "+f"((acc)[1]), "+f"((acc)[2]), "+f"((acc)[3])         \
        : "r"(__float_as_uint(a0)), "r"(__float_as_uint(a1)),                    \
          "r"(__float_as_uint(a2)), "r"(__float_as_uint(a3)),                    \
          "r"(__float_as_uint(b0)), "r"(__float_as_uint(b1)))

template<int EPI>
__global__ __launch_bounds__(256, 2) void mma_gemm(
    const float* __restrict__ A, int lda, const float* __restrict__ B,
    float* __restrict__ C, const float* __restrict__ bias,
    const float* __restrict__ mul, int ldmul, int K, int N) {
    extern __shared__ float sm[];
    const int tid = threadIdx.x;
    const int lane = tid & 31, wid = tid >> 5;
    const int g = lane >> 2, tg = lane & 3;
    const int wm = (wid & 3) * 32, wn = (wid >> 2) * 64;
    const int bm = blockIdx.y * 128, bn = blockIdx.x * 128;
    const int S = K >> 5;
    const uint32_t sbase = s2u(sm);

    const float* Ab = A + (size_t)bm * lda;
    const float* Bb = B + (size_t)bn * K;

    float acc[2][8][4];
    #pragma unroll
    for (int mt = 0; mt < 2; mt++)
        #pragma unroll
        for (int nt = 0; nt < 8; nt++)
            #pragma unroll
            for (int j = 0; j < 4; j++) acc[mt][nt][j] = 0.f;

    auto issue = [&](int st, int k0) {
        uint32_t sA = sbase + (uint32_t)(st * STAGEF) * 4;
        uint32_t sB = sA + (uint32_t)TILEF * 4;
        #pragma unroll
        for (int r = 0; r < 4; r++) {
            int i = tid + r * 256;
            int row = i >> 3, c4 = (i & 7) * 4;
            cp16(sA + (uint32_t)(row * PS + c4) * 4, Ab + (size_t)row * lda + k0 + c4);
            int ok = (bn + row < N) ? 16 : 0;
            cp16p(sB + (uint32_t)(row * PS + c4) * 4,
                  ok ? (Bb + (size_t)row * K + k0 + c4) : B, ok);
        }
        asm volatile("cp.async.commit_group;" ::: "memory");
    };

    issue(0, 0);

    for (int s = 0; s < S; s++) {
        asm volatile("cp.async.wait_group 0;" ::: "memory");
        __syncthreads();

        if (s + 1 < S) issue((s + 1) & 1, (s + 1) * 32);

        const float* As = sm + (s & 1) * STAGEF;
        const float* Bs = As + TILEF;

        #pragma unroll
        for (int half = 0; half < 2; half++) {
            const int kb = half * 16 + 4 * tg;
            float4 aLo[2], aHi[2];
            #pragma unroll
            for (int mt = 0; mt < 2; mt++) {
                int m0 = wm + mt * 16 + g;
                aLo[mt] = *(const float4*)&As[m0 * PS + kb];
                aHi[mt] = *(const float4*)&As[(m0 + 8) * PS + kb];
            }
            #pragma unroll
            for (int nt = 0; nt < 8; nt++) {
                int n0 = wn + nt * 8 + g;
                float4 bv = *(const float4*)&Bs[n0 * PS + kb];
                #pragma unroll
                for (int mt = 0; mt < 2; mt++) {
                    MMA_TF32(acc[mt][nt], aLo[mt].x, aHi[mt].x, aLo[mt].y, aHi[mt].y,
                             bv.x, bv.y);
                    MMA_TF32(acc[mt][nt], aLo[mt].z, aHi[mt].z, aLo[mt].w, aHi[mt].w,
                             bv.z, bv.w);
                }
            }
        }
        __syncthreads();
    }

    // epilogue (output mapping unchanged: c0,c1 -> row g cols 2tg,2tg+1; c2,c3 -> row g+8)
    #pragma unroll
    for (int mt = 0; mt < 2; mt++) {
        int gm0 = bm + wm + mt * 16 + g;
        #pragma unroll
        for (int nt = 0; nt < 8; nt++) {
            int gn = bn + wn + nt * 8 + 2 * tg;
            if (gn < N) {
                float b0 = bias[gn], b1 = bias[gn + 1];
                float v0 = acc[mt][nt][0] + b0;
                float v1 = acc[mt][nt][1] + b1;
                float v2 = acc[mt][nt][2] + b0;
                float v3 = acc[mt][nt][3] + b1;
                if (EPI == 0) {
                    v0 = tf32r(fmaxf(v0, 0.f)); v1 = tf32r(fmaxf(v1, 0.f));
                    v2 = tf32r(fmaxf(v2, 0.f)); v3 = tf32r(fmaxf(v3, 0.f));
                } else {
                    float2 m0v = *(const float2*)(mul + (size_t)gm0 * ldmul + gn);
                    float2 m1v = *(const float2*)(mul + (size_t)(gm0 + 8) * ldmul + gn);
                    v0 *= m0v.x; v1 *= m0v.y; v2 *= m1v.x; v3 *= m1v.y;
                }
                float2 o0 = {v0, v1}, o1 = {v2, v3};
                *(float2*)(C + (size_t)gm0 * N + gn) = o0;
                *(float2*)(C + (size_t)(gm0 + 8) * N + gn) = o1;
            }
        }
    }
}

// ---------------- attention: dot, softmax(4), weighted sum (float4) --------
__global__ __launch_bounds__(192) void attn_kernel() {
    const int bq = blockIdx.x;
    const int tid = threadIdx.x;
    const float4* q4  = (const float4*)(g_QRY + (size_t)bq * CK);
    const float4* pk4 = (const float4*)(g_PK + (size_t)bq * 4 * CK);
    const float4* pv4 = (const float4*)(g_PV + (size_t)bq * 4 * CK);

    float p[4] = {0.f, 0.f, 0.f, 0.f};
    if (tid < 144) {                       // CK/4 = 144
        float4 q = q4[tid];
        #pragma unroll
        for (int s = 0; s < 4; s++) {
            float4 k = pk4[s * 144 + tid];
            p[s] = q.x * k.x + q.y * k.y + q.z * k.z + q.w * k.w;
        }
    }
    #pragma unroll
    for (int off = 16; off; off >>= 1)
        #pragma unroll
        for (int s = 0; s < 4; s++)
            p[s] += __shfl_down_sync(0xffffffffu, p[s], off);

    __shared__ float red[4][6];
    __shared__ float wsm[4];
    int warp = tid >> 5, lane = tid & 31;
    if (lane == 0)
        #pragma unroll
        for (int s = 0; s < 4; s++) red[s][warp] = p[s];
    __syncthreads();
    if (tid == 0) {
        float attn[4];
        #pragma unroll
        for (int s = 0; s < 4; s++)
            attn[s] = red[s][0] + red[s][1] + red[s][2] + red[s][3] + red[s][4] + red[s][5];
        float m = fmaxf(fmaxf(attn[0], attn[1]), fmaxf(attn[2], attn[3]));
        float e[4], t = 0.f;
        #pragma unroll
        for (int s = 0; s < 4; s++) { e[s] = expf(attn[s] - m); t += e[s]; }
        float inv = 1.0f / t;
        #pragma unroll
        for (int s = 0; s < 4; s++) wsm[s] = e[s] * inv;
    }
    __syncthreads();
    if (tid < 144) {
        float w0 = wsm[0], w1 = wsm[1], w2 = wsm[2], w3 = wsm[3];
        float4 v0 = pv4[tid], v1 = pv4[144 + tid], v2 = pv4[288 + tid], v3 = pv4[432 + tid];
        float4 x;
        x.x = tf32r(w0 * v0.x + w1 * v1.x + w2 * v2.x + w3 * v3.x);
        x.y = tf32r(w0 * v0.y + w1 * v1.y + w2 * v2.y + w3 * v3.y);
        x.z = tf32r(w0 * v0.z + w1 * v1.z + w2 * v2.z + w3 * v3.z);
        x.w = tf32r(w0 * v0.w + w1 * v1.w + w2 * v2.w + w3 * v3.w);
        ((float4*)(g_X + (size_t)bq * CK))[tid] = x;
    }
}

// ---------------- final projection: [8192,256] @ [256,3] + bias ------------
__global__ __launch_bounds__(128) void outproj_kernel(
    const float* __restrict__ qW2, const float* __restrict__ qb2,
    float* __restrict__ out) {
    int warp = threadIdx.x >> 5, lane = threadIdx.x & 31;
    int row = blockIdx.x * 4 + warp;
    const float* h = g_Hq + (size_t)row * HID;
    float a0 = 0.f, a1 = 0.f, a2 = 0.f;
    #pragma unroll
    for (int i = 0; i < 8; i++) {
        int k = i * 32 + lane;
        float a = h[k];
        a0 += a * qW2[k * 3 + 0];
        a1 += a * qW2[k * 3 + 1];
        a2 += a * qW2[k * 3 + 2];
    }
    #pragma unroll
    for (int off = 16; off; off >>= 1) {
        a0 += __shfl_down_sync(0xffffffffu, a0, off);
        a1 += __shfl_down_sync(0xffffffffu, a1, off);
        a2 += __shfl_down_sync(0xffffffffu, a2, off);
    }
    if (lane == 0) {
        out[row * 3 + 0] = a0 + qb2[0];
        out[row * 3 + 1] = a1 + qb2[1];
        out[row * 3 + 2] = a2 + qb2[2];
    }
}

// ---------------- launch ---------------------------------------------------
extern "C" void kernel_launch(void* const* d_in, const int* in_sizes, int n_in,
                              void* d_out, int out_size) {
    const float* feature = (const float*)d_in[0];
    const float* coord   = (const float*)d_in[1];
    const float* scale   = (const float*)d_in[2];
    const float* kW1 = (const float*)d_in[3];
    const float* kb1 = (const float*)d_in[4];
    const float* kW2 = (const float*)d_in[5];
    const float* kb2 = (const float*)d_in[6];
    const float* vW1 = (const float*)d_in[7];
    const float* vb1 = (const float*)d_in[8];
    const float* vW2 = (const float*)d_in[9];
    const float* vb2 = (const float*)d_in[10];
    const float* qW1 = (const float*)d_in[11];
    const float* qb1 = (const float*)d_in[12];
    const float* qW2 = (const float*)d_in[13];
    const float* qb2 = (const float*)d_in[14];
    float* out = (float*)d_out;

    float *pINP, *pH, *pPK, *pPV, *pX, *pHq, *pW1t, *pb1, *pkW2t, *pvW2t, *pqW1t;
    cudaGetSymbolAddress((void**)&pINP,  g_INP);
    cudaGetSymbolAddress((void**)&pH,    g_H);
    cudaGetSymbolAddress((void**)&pPK,   g_PK);
    cudaGetSymbolAddress((void**)&pPV,   g_PV);
    cudaGetSymbolAddress((void**)&pX,    g_X);
    cudaGetSymbolAddress((void**)&pHq,   g_Hq);
    cudaGetSymbolAddress((void**)&pW1t,  g_W1t);
    cudaGetSymbolAddress((void**)&pb1,   g_b1);
    cudaGetSymbolAddress((void**)&pkW2t, g_kW2t);
    cudaGetSymbolAddress((void**)&pvW2t, g_vW2t);
    cudaGetSymbolAddress((void**)&pqW1t, g_qW1t);

    cudaFuncSetAttribute(mma_gemm<0>, cudaFuncAttributeMaxDynamicSharedMemorySize, SMEMB);
    cudaFuncSetAttribute(mma_gemm<1>, cudaFuncAttributeMaxDynamicSharedMemorySize, SMEMB);

    // 0) transpose/pad/round weights (fused W1)
    prep_weights<<<(512 * KINP + 255) / 256, 256>>>(kW1, vW1, kW2, vW2, qW1, kb1, vb1);

    // 1) gather/setup
    setup_kernel<<<NROW, 128>>>(feature, coord, scale);

    // 2) fused layer-1:  H[:, 0:512] = tf32r(relu(INP @ W1t^T + b1)), K=608
    {
        dim3 grid(4, NROW4 / 128);
        mma_gemm<0><<<grid, 256, SMEMB>>>(pINP, KINP, pW1t, pH, pb1, nullptr, 0, KINP, 512);
    }

    // 3) layer-2 MLPs:  P = kv * (H @ W2t^T + b2)    [32768 x 576], K=256
    {
        dim3 grid((CK + 127) / 128, NROW4 / 128);
        mma_gemm<1><<<grid, 256, SMEMB>>>(pH,       512, pkW2t, pPK, kb2, pINP, KINP, HID, CK);
        mma_gemm<1><<<grid, 256, SMEMB>>>(pH + 256, 512, pvW2t, pPV, vb2, pINP, KINP, HID, CK);
    }

    // 4) attention + softmax + weighted sum -> X     [8192 x 576]
    attn_kernel<<<NROW, 192>>>();

    // 5) query MLP layer 1: Hq = relu(X @ qW1t^T + qb1)  [8192 x 256], K=576
    {
        dim3 grid(2, NROW / 128);
        mma_gemm<0><<<grid, 256, SMEMB>>>(pX, CK, pqW1t, pHq, qb1, nullptr, 0, CK, HID);
    }

    // 6) output projection  [8192 x 3]
    outproj_kernel<<<NROW / 4, 128>>>(qW2, qb2, out);
}

// round 7
// speedup vs baseline: 1.5365x; 1.5365x over previous
#include <cuda_runtime.h>
#include <cuda_fp16.h>
#include <math.h>
#include <stdint.h>

// Problem constants
#define BB 2
#define QQ 4096
#define CC 64
#define HH 64
#define WW 64
#define CK 576          // C*9
#define KIN 580         // CK + 4
#define KINP 608        // padded to multiple of 32
#define HID 256
#define NROW (BB*QQ)        // 8192
#define NROW4 (BB*QQ*4)     // 32768

// ---------------- scratch (device globals; no allocation) ----------------
__device__ __half g_INPh[NROW4 * KINP];   // [32768, 608]
__device__ float  g_QRY [NROW * CK];      // [8192, 576] fp32
__device__ __half g_Hh  [NROW4 * 512];    // cols 0..255 Hk, 256..511 Hv
__device__ __half g_PKh [NROW4 * CK];
__device__ __half g_PVh [NROW4 * CK];
__device__ __half g_Xh  [NROW * CK];
__device__ __half g_Hqh [NROW * HID];
// weights, [N, K] K-major, fp16
__device__ __half g_W1t [512 * KINP];     // kW1t rows 0..255, vW1t rows 256..511
__device__ float  g_b1  [512];
__device__ __half g_kW2t[CK * HID];
__device__ __half g_vW2t[CK * HID];
__device__ __half g_qW1t[HID * CK];

__device__ __forceinline__ uint32_t s2u(const void* p) {
    uint32_t a;
    asm("{ .reg .u64 t; cvta.to.shared.u64 t, %1; cvt.u32.u64 %0, t; }" : "=r"(a) : "l"(p));
    return a;
}

// ---------------- weight transpose / pad / fp16 ----------------------------
__global__ void prep_weights(const float* __restrict__ kW1, const float* __restrict__ vW1,
                             const float* __restrict__ kW2, const float* __restrict__ vW2,
                             const float* __restrict__ qW1,
                             const float* __restrict__ kb1, const float* __restrict__ vb1) {
    int i = blockIdx.x * 256 + threadIdx.x;
    if (i < 512 * KINP) {           // fused W1: [512, 608]
        int n = i / KINP, k = i - n * KINP;
        float v = 0.f;
        if (k < KIN) v = (n < HID) ? kW1[k * HID + n] : vW1[k * HID + (n - HID)];
        g_W1t[i] = __float2half_rn(v);
    }
    if (i < CK * HID) {             // [576, 256] from [256, 576]
        int n = i / HID, k = i - n * HID;
        g_kW2t[i] = __float2half_rn(kW2[k * CK + n]);
        g_vW2t[i] = __float2half_rn(vW2[k * CK + n]);
    }
    if (i < HID * CK) {             // [256, 576] from [576, 256]
        int n = i / CK, k = i - n * CK;
        g_qW1t[i] = __float2half_rn(qW1[k * HID + n]);
    }
    if (i < 512)
        g_b1[i] = (i < HID) ? kb1[i] : vb1[i - HID];
}

// ---------------- setup: gather unfold samples, build INP + query ----------
__device__ __forceinline__ int nearest_idx(float c) {
    float f = ((c + 1.0f) * 64.0f - 1.0f) * 0.5f + 0.5f;
    int i = (int)floorf(f);
    return i < 0 ? 0 : (i > 63 ? 63 : i);
}

__global__ __launch_bounds__(128) void setup_kernel(
    const float* __restrict__ feature, const float* __restrict__ coord,
    const float* __restrict__ scale) {
    const int bq = blockIdx.x;
    const int b  = bq >> 12;
    const int tid = threadIdx.x;

    const float cy = coord[bq * 2 + 0];
    const float cx = coord[bq * 2 + 1];
    const float s0 = scale[bq * 2 + 0];
    const float s1 = scale[bq * 2 + 1];
    const float lo = -1.0f + 1e-6f, hi = 1.0f - 1e-6f;

    int   qy[4], qx[4];
    float area[4];
    const float rx = 1.0f / 64.0f, ry = 1.0f / 64.0f;
    #pragma unroll
    for (int s = 0; s < 4; s++) {
        float vx = (s >= 2) ? 1.0f : -1.0f;
        float vy = (s & 1)  ? 1.0f : -1.0f;
        float c0 = fminf(fmaxf(cy + vx * rx + 1e-6f, lo), hi);
        float c1 = fminf(fmaxf(cx + vy * ry + 1e-6f, lo), hi);
        int iy = nearest_idx(c0), ix = nearest_idx(c1);
        qy[s] = iy; qx[s] = ix;
        float qc0 = -1.0f + (2.0f * iy + 1.0f) / 64.0f;
        float qc1 = -1.0f + (2.0f * ix + 1.0f) / 64.0f;
        area[s] = fabsf((cy - qc0) * 64.0f * (cx - qc1) * 64.0f) + 1e-9f;
    }
    float tot = area[0] + area[1] + area[2] + area[3];
    float qw[4];
    #pragma unroll
    for (int s = 0; s < 4; s++) qw[s] = area[3 - s] / tot;

    const float sc00 = scale[(b * QQ) * 2 + 0];
    const float sc01 = scale[(b * QQ) * 2 + 1];
    const float invtx = (1.0f - sc00) / 63.0f;
    const float invty = (1.0f - sc01) / 63.0f;
    int   ky[4], kx[4];
    float kr0[4], kr1[4];
    #pragma unroll
    for (int s = 0; s < 4; s++) {
        float vx = (s >= 2) ? 1.0f : -1.0f;
        float vy = (s & 1)  ? 1.0f : -1.0f;
        float c0 = fminf(fmaxf(cy + vx * invtx + 1e-6f, lo), hi);
        float c1 = fminf(fmaxf(cx + vy * invty + 1e-6f, lo), hi);
        int iy = nearest_idx(c0), ix = nearest_idx(c1);
        ky[s] = iy; kx[s] = ix;
        float qc0 = -1.0f + (2.0f * iy + 1.0f) / 64.0f;
        float qc1 = -1.0f + (2.0f * ix + 1.0f) / 64.0f;
        kr0[s] = (cy - qc0) * 64.0f;
        kr1[s] = (cx - qc1) * 64.0f;
    }

    const float* fb = feature + (size_t)b * CC * HH * WW;
    for (int k = tid; k < CK; k += 128) {
        int c = k / 9, p = k - c * 9;
        int di = p / 3 - 1, dj = p - (p / 3) * 3 - 1;
        const float* fc = fb + (size_t)c * (HH * WW);
        float qacc = 0.f;
        #pragma unroll
        for (int s = 0; s < 4; s++) {
            int y = qy[s] + di, x = qx[s] + dj;
            float v = ((unsigned)y < 64u && (unsigned)x < 64u) ? fc[y * 64 + x] : 0.f;
            qacc += qw[s] * v;
        }
        g_QRY[(size_t)bq * CK + k] = qacc;
        #pragma unroll
        for (int s = 0; s < 4; s++) {
            int y = ky[s] + di, x = kx[s] + dj;
            float v = ((unsigned)y < 64u && (unsigned)x < 64u) ? fc[y * 64 + x] : 0.f;
            g_INPh[((size_t)(bq * 4 + s)) * KINP + k] = __float2half_rn(v);
        }
    }
    {   // cols 576..607: rel(2), scale(2), zeros. 128 thr = 4 shifts x 32 cols.
        int s = tid >> 5, cc = tid & 31;
        float v = 0.f;
        if (cc == 0) v = kr0[s];
        else if (cc == 1) v = kr1[s];
        else if (cc == 2) v = s0 * 64.0f;
        else if (cc == 3) v = s1 * 64.0f;
        g_INPh[((size_t)(bq * 4 + s)) * KINP + 576 + cc] = __float2half_rn(v);
    }
}

// ---------------- fp16 mma.sync GEMM ---------------------------------------
// C[M,N] = A[M,K(lda)] @ B[N,K]^T, all half, fp32 accumulate.
// BM=128, BN=128, BK=32, 3-stage cp.async.  K%32==0, M%128==0, N-edge guarded.
// k-permutation: lane tg holds k=8tg..8tg+7 via one LDS.128 per fragment;
// identical remap on A and B -> exact same dot products as spec layout.
// Smem tile: 128 rows x 32 halves (64B rows), stride 16 words -> conflict-free.
// EPI 0: half(relu(acc+bias)).  EPI 1: half((acc+bias)*mul[gm*ldmul+gn]).
#define TILEB 8192                  // bytes per operand tile
#define STAGEB 16384
#define SMEMB (3*STAGEB)            // 49152

__device__ __forceinline__ void cp16(uint32_t dst, const __half* src) {
    asm volatile("cp.async.cg.shared.global [%0], [%1], 16;" :: "r"(dst), "l"(src) : "memory");
}
__device__ __forceinline__ void cp16p(uint32_t dst, const __half* src, int sz) {
    asm volatile("cp.async.cg.shared.global [%0], [%1], 16, %2;" :: "r"(dst), "l"(src), "r"(sz) : "memory");
}
#define MMA_F16(acc, a0, a1, a2, a3, b0, b1)                                     \
    asm volatile("mma.sync.aligned.m16n8k16.row.col.f32.f16.f16.f32 "            \
        "{%0,%1,%2,%3}, {%4,%5,%6,%7}, {%8,%9}, {%0,%1,%2,%3};"                  \
        : "+f"((acc)[0]), "+f"((acc)[1]), "+f"((acc)[2]), "+f"((acc)[3])         \
        : "r"(a0), "r"(a1), "r"(a2), "r"(a3), "r"(b0), "r"(b1))

template<int EPI>
__global__ __launch_bounds__(256, 2) void mma_gemm(
    const __half* __restrict__ A, int lda, const __half* __restrict__ B,
    __half* __restrict__ C, const float* __restrict__ bias,
    const __half* __restrict__ mul, int ldmul, int K, int N) {
    extern __shared__ char smem[];
    const int tid = threadIdx.x;
    const int lane = tid & 31, wid = tid >> 5;
    const int g = lane >> 2, tg = lane & 3;
    const int wm = (wid & 3) * 32, wn = (wid >> 2) * 64;
    const int bm = blockIdx.y * 128, bn = blockIdx.x * 128;
    const int S = K >> 5;
    const uint32_t sbase = s2u(smem);

    const __half* Ab = A + (size_t)bm * lda;
    const __half* Bb = B + (size_t)bn * K;

    float acc[2][8][4];
    #pragma unroll
    for (int mt = 0; mt < 2; mt++)
        #pragma unroll
        for (int nt = 0; nt < 8; nt++)
            #pragma unroll
            for (int j = 0; j < 4; j++) acc[mt][nt][j] = 0.f;

    auto issue = [&](int st, int k0) {
        uint32_t aB = sbase + (uint32_t)(st * STAGEB);
        uint32_t bB = aB + TILEB;
        #pragma unroll
        for (int r = 0; r < 2; r++) {
            int c = tid + r * 256;          // 512 chunks of 16B per tile
            int row = c >> 2, q = c & 3;    // 4 x 16B per 64B row
            cp16(aB + (uint32_t)(row * 64 + q * 16), Ab + (size_t)row * lda + k0 + q * 8);
            int ok = (bn + row < N) ? 16 : 0;
            cp16p(bB + (uint32_t)(row * 64 + q * 16),
                  ok ? (Bb + (size_t)row * K + k0 + q * 8) : B, ok);
        }
        asm volatile("cp.async.commit_group;" ::: "memory");
    };

    issue(0, 0);
    issue(1, 32);

    for (int s = 0; s < S; s++) {
        asm volatile("cp.async.wait_group 1;" ::: "memory");
        __syncthreads();

        if (s + 2 < S) issue((s + 2) % 3, (s + 2) * 32);

        const __half* As = (const __half*)(smem + (s % 3) * STAGEB);
        const __half* Bs = As + TILEB / 2;

        uint4 a0[2], a1[2];
        #pragma unroll
        for (int mt = 0; mt < 2; mt++) {
            int m0 = wm + mt * 16 + g;
            a0[mt] = *(const uint4*)(As + m0 * 32 + 8 * tg);
            a1[mt] = *(const uint4*)(As + (m0 + 8) * 32 + 8 * tg);
        }
        #pragma unroll
        for (int nt = 0; nt < 8; nt++) {
            int n0 = wn + nt * 8 + g;
            uint4 bv = *(const uint4*)(Bs + n0 * 32 + 8 * tg);
            #pragma unroll
            for (int mt = 0; mt < 2; mt++) {
                MMA_F16(acc[mt][nt], a0[mt].x, a1[mt].x, a0[mt].y, a1[mt].y, bv.x, bv.y);
                MMA_F16(acc[mt][nt], a0[mt].z, a1[mt].z, a0[mt].w, a1[mt].w, bv.z, bv.w);
            }
        }
        __syncthreads();
    }

    // epilogue: c0,c1 -> row g cols 2tg,2tg+1; c2,c3 -> row g+8
    #pragma unroll
    for (int mt = 0; mt < 2; mt++) {
        int gm0 = bm + wm + mt * 16 + g;
        #pragma unroll
        for (int nt = 0; nt < 8; nt++) {
            int gn = bn + wn + nt * 8 + 2 * tg;
            if (gn < N) {
                float b0 = bias[gn], b1 = bias[gn + 1];
                float v0 = acc[mt][nt][0] + b0;
                float v1 = acc[mt][nt][1] + b1;
                float v2 = acc[mt][nt][2] + b0;
                float v3 = acc[mt][nt][3] + b1;
                if (EPI == 0) {
                    v0 = fmaxf(v0, 0.f); v1 = fmaxf(v1, 0.f);
                    v2 = fmaxf(v2, 0.f); v3 = fmaxf(v3, 0.f);
                } else {
                    float2 m0v = __half22float2(*(const __half2*)(mul + (size_t)gm0 * ldmul + gn));
                    float2 m1v = __half22float2(*(const __half2*)(mul + (size_t)(gm0 + 8) * ldmul + gn));
                    v0 *= m0v.x; v1 *= m0v.y; v2 *= m1v.x; v3 *= m1v.y;
                }
                *(__half2*)(C + (size_t)gm0 * N + gn) = __floats2half2_rn(v0, v1);
                *(__half2*)(C + (size_t)(gm0 + 8) * N + gn) = __floats2half2_rn(v2, v3);
            }
        }
    }
}

// ---------------- attention: dot, softmax(4), weighted sum -----------------
__global__ __launch_bounds__(192) void attn_kernel() {
    const int bq = blockIdx.x;
    const int tid = threadIdx.x;
    const float4* q4 = (const float4*)(g_QRY + (size_t)bq * CK);
    const __half* pk = g_PKh + (size_t)bq * 4 * CK;
    const __half* pv = g_PVh + (size_t)bq * 4 * CK;

    float p[4] = {0.f, 0.f, 0.f, 0.f};
    if (tid < 144) {                       // CK/4 = 144, 4 halves per thread
        float4 q = q4[tid];
        #pragma unroll
        for (int s = 0; s < 4; s++) {
            uint2 u = *(const uint2*)(pk + (size_t)s * CK + tid * 4);
            float2 f0 = __half22float2(*(__half2*)&u.x);
            float2 f1 = __half22float2(*(__half2*)&u.y);
            p[s] = q.x * f0.x + q.y * f0.y + q.z * f1.x + q.w * f1.y;
        }
    }
    #pragma unroll
    for (int off = 16; off; off >>= 1)
        #pragma unroll
        for (int s = 0; s < 4; s++)
            p[s] += __shfl_down_sync(0xffffffffu, p[s], off);

    __shared__ float red[4][6];
    __shared__ float wsm[4];
    int warp = tid >> 5, lane = tid & 31;
    if (lane == 0)
        #pragma unroll
        for (int s = 0; s < 4; s++) red[s][warp] = p[s];
    __syncthreads();
    if (tid == 0) {
        float attn[4];
        #pragma unroll
        for (int s = 0; s < 4; s++)
            attn[s] = red[s][0] + red[s][1] + red[s][2] + red[s][3] + red[s][4] + red[s][5];
        float m = fmaxf(fmaxf(attn[0], attn[1]), fmaxf(attn[2], attn[3]));
        float e[4], t = 0.f;
        #pragma unroll
        for (int s = 0; s < 4; s++) { e[s] = expf(attn[s] - m); t += e[s]; }
        float inv = 1.0f / t;
        #pragma unroll
        for (int s = 0; s < 4; s++) wsm[s] = e[s] * inv;
    }
    __syncthreads();
    if (tid < 144) {
        float x0 = 0.f, x1 = 0.f, x2 = 0.f, x3 = 0.f;
        #pragma unroll
        for (int s = 0; s < 4; s++) {
            float w = wsm[s];
            uint2 u = *(const uint2*)(pv + (size_t)s * CK + tid * 4);
            float2 f0 = __half22float2(*(__half2*)&u.x);
            float2 f1 = __half22float2(*(__half2*)&u.y);
            x0 += w * f0.x; x1 += w * f0.y; x2 += w * f1.x; x3 += w * f1.y;
        }
        __half2* xp = (__half2*)(g_Xh + (size_t)bq * CK);
        xp[tid * 2 + 0] = __floats2half2_rn(x0, x1);
        xp[tid * 2 + 1] = __floats2half2_rn(x2, x3);
    }
}

// ---------------- final projection: [8192,256] @ [256,3] + bias ------------
__global__ __launch_bounds__(128) void outproj_kernel(
    const float* __restrict__ qW2, const float* __restrict__ qb2,
    float* __restrict__ out) {
    int warp = threadIdx.x >> 5, lane = threadIdx.x & 31;
    int row = blockIdx.x * 4 + warp;
    const __half* h = g_Hqh + (size_t)row * HID;
    float a0 = 0.f, a1 = 0.f, a2 = 0.f;
    #pragma unroll
    for (int i = 0; i < 8; i++) {
        int k = i * 32 + lane;
        float a = __half2float(h[k]);
        a0 += a * qW2[k * 3 + 0];
        a1 += a * qW2[k * 3 + 1];
        a2 += a * qW2[k * 3 + 2];
    }
    #pragma unroll
    for (int off = 16; off; off >>= 1) {
        a0 += __shfl_down_sync(0xffffffffu, a0, off);
        a1 += __shfl_down_sync(0xffffffffu, a1, off);
        a2 += __shfl_down_sync(0xffffffffu, a2, off);
    }
    if (lane == 0) {
        out[row * 3 + 0] = a0 + qb2[0];
        out[row * 3 + 1] = a1 + qb2[1];
        out[row * 3 + 2] = a2 + qb2[2];
    }
}

// ---------------- launch ---------------------------------------------------
extern "C" void kernel_launch(void* const* d_in, const int* in_sizes, int n_in,
                              void* d_out, int out_size) {
    const float* feature = (const float*)d_in[0];
    const float* coord   = (const float*)d_in[1];
    const float* scale   = (const float*)d_in[2];
    const float* kW1 = (const float*)d_in[3];
    const float* kb1 = (const float*)d_in[4];
    const float* kW2 = (const float*)d_in[5];
    const float* kb2 = (const float*)d_in[6];
    const float* vW1 = (const float*)d_in[7];
    const float* vb1 = (const float*)d_in[8];
    const float* vW2 = (const float*)d_in[9];
    const float* vb2 = (const float*)d_in[10];
    const float* qW1 = (const float*)d_in[11];
    const float* qb1 = (const float*)d_in[12];
    const float* qW2 = (const float*)d_in[13];
    const float* qb2 = (const float*)d_in[14];
    float* out = (float*)d_out;

    __half *pINP, *pH, *pPK, *pPV, *pX, *pHq, *pW1t, *pkW2t, *pvW2t, *pqW1t;
    float *pb1;
    cudaGetSymbolAddress((void**)&pINP,  g_INPh);
    cudaGetSymbolAddress((void**)&pH,    g_Hh);
    cudaGetSymbolAddress((void**)&pPK,   g_PKh);
    cudaGetSymbolAddress((void**)&pPV,   g_PVh);
    cudaGetSymbolAddress((void**)&pX,    g_Xh);
    cudaGetSymbolAddress((void**)&pHq,   g_Hqh);
    cudaGetSymbolAddress((void**)&pW1t,  g_W1t);
    cudaGetSymbolAddress((void**)&pb1,   g_b1);
    cudaGetSymbolAddress((void**)&pkW2t, g_kW2t);
    cudaGetSymbolAddress((void**)&pvW2t, g_vW2t);
    cudaGetSymbolAddress((void**)&pqW1t, g_qW1t);

    cudaFuncSetAttribute(mma_gemm<0>, cudaFuncAttributeMaxDynamicSharedMemorySize, SMEMB);
    cudaFuncSetAttribute(mma_gemm<1>, cudaFuncAttributeMaxDynamicSharedMemorySize, SMEMB);

    // 0) transpose/pad weights -> fp16
    prep_weights<<<(512 * KINP + 255) / 256, 256>>>(kW1, vW1, kW2, vW2, qW1, kb1, vb1);

    // 1) gather/setup
    setup_kernel<<<NROW, 128>>>(feature, coord, scale);

    // 2) fused layer-1:  H[:, 0:512] = relu(INP @ W1t^T + b1), K=608
    {
        dim3 grid(4, NROW4 / 128);
        mma_gemm<0><<<grid, 256, SMEMB>>>(pINP, KINP, pW1t, pH, pb1, nullptr, 0, KINP, 512);
    }

    // 3) layer-2 MLPs:  P = kv * (H @ W2t^T + b2)    [32768 x 576], K=256
    {
        dim3 grid((CK + 127) / 128, NROW4 / 128);
        mma_gemm<1><<<grid, 256, SMEMB>>>(pH,       512, pkW2t, pPK, kb2, pINP, KINP, HID, CK);
        mma_gemm<1><<<grid, 256, SMEMB>>>(pH + 256, 512, pvW2t, pPV, vb2, pINP, KINP, HID, CK);
    }

    // 4) attention + softmax + weighted sum -> X     [8192 x 576]
    attn_kernel<<<NROW, 192>>>();

    // 5) query MLP layer 1: Hq = relu(X @ qW1t^T + qb1)  [8192 x 256], K=576
    {
        dim3 grid(2, NROW / 128);
        mma_gemm<0><<<grid, 256, SMEMB>>>(pX, CK, pqW1t, pHq, qb1, nullptr, 0, CK, HID);
    }

    // 6) output projection  [8192 x 3]
    outproj_kernel<<<NROW / 4, 128>>>(qW2, qb2, out);
}

// round 8
// speedup vs baseline: 1.6012x; 1.0421x over previous
#include <cuda_runtime.h>
#include <cuda_fp16.h>
#include <math.h>
#include <stdint.h>

// Problem constants
#define BB 2
#define QQ 4096
#define CC 64
#define HH 64
#define WW 64
#define CK 576          // C*9
#define KIN 580         // CK + 4
#define KINP 608        // K padding for layer-1 (mult of 32)
#define CKP 640         // N padding for layer-2 (mult of 128)
#define HID 256
#define NROW (BB*QQ)        // 8192
#define NROW4 (BB*QQ*4)     // 32768

// ---------------- scratch (device globals; no allocation) ----------------
__device__ __half g_INPh[NROW4 * KINP + 64];  // [32768, 608] (+64 pad: unguarded epi-mul read)
__device__ float  g_QRY [NROW * CK];          // [8192, 576] fp32
__device__ __half g_Hh  [NROW4 * 512];        // cols 0..255 Hk, 256..511 Hv
__device__ __half g_PKh [NROW4 * CKP];        // stride 640
__device__ __half g_PVh [NROW4 * CKP];
__device__ __half g_Xh  [NROW * CK];
__device__ __half g_Hqh [NROW * HID];
// weights, [N, K] K-major, fp16
__device__ __half g_W1t [512 * KINP];         // kW1t rows 0..255, vW1t rows 256..511
__device__ float  g_b1  [512];
__device__ __half g_kW2t[CKP * HID];          // rows 576..639 zero
__device__ __half g_vW2t[CKP * HID];
__device__ float  g_kb2p[CKP];                // padded biases
__device__ float  g_vb2p[CKP];
__device__ __half g_qW1t[HID * CK];

__device__ __forceinline__ uint32_t s2u(const void* p) {
    uint32_t a;
    asm("{ .reg .u64 t; cvta.to.shared.u64 t, %1; cvt.u32.u64 %0, t; }" : "=r"(a) : "l"(p));
    return a;
}

// ---------------- weight transpose / pad / fp16 ----------------------------
__global__ void prep_weights(const float* __restrict__ kW1, const float* __restrict__ vW1,
                             const float* __restrict__ kW2, const float* __restrict__ vW2,
                             const float* __restrict__ qW1,
                             const float* __restrict__ kb1, const float* __restrict__ vb1,
                             const float* __restrict__ kb2, const float* __restrict__ vb2) {
    int i = blockIdx.x * 256 + threadIdx.x;
    if (i < 512 * KINP) {           // fused W1: [512, 608]
        int n = i / KINP, k = i - n * KINP;
        float v = 0.f;
        if (k < KIN) v = (n < HID) ? kW1[k * HID + n] : vW1[k * HID + (n - HID)];
        g_W1t[i] = __float2half_rn(v);
    }
    if (i < CKP * HID) {            // [640, 256] from [256, 576], zero rows >= 576
        int n = i / HID, k = i - n * HID;
        float a = 0.f, b = 0.f;
        if (n < CK) { a = kW2[k * CK + n]; b = vW2[k * CK + n]; }
        g_kW2t[i] = __float2half_rn(a);
        g_vW2t[i] = __float2half_rn(b);
    }
    if (i < HID * CK) {             // [256, 576] from [576, 256]
        int n = i / CK, k = i - n * CK;
        g_qW1t[i] = __float2half_rn(qW1[k * HID + n]);
    }
    if (i < 512)
        g_b1[i] = (i < HID) ? kb1[i] : vb1[i - HID];
    if (i < CKP) {
        g_kb2p[i] = (i < CK) ? kb2[i] : 0.f;
        g_vb2p[i] = (i < CK) ? vb2[i] : 0.f;
    }
}

// ---------------- setup: gather unfold samples, build INP + query ----------
__device__ __forceinline__ int nearest_idx(float c) {
    float f = ((c + 1.0f) * 64.0f - 1.0f) * 0.5f + 0.5f;
    int i = (int)floorf(f);
    return i < 0 ? 0 : (i > 63 ? 63 : i);
}

__global__ __launch_bounds__(128) void setup_kernel(
    const float* __restrict__ feature, const float* __restrict__ coord,
    const float* __restrict__ scale) {
    const int bq = blockIdx.x;
    const int b  = bq >> 12;
    const int tid = threadIdx.x;

    const float cy = coord[bq * 2 + 0];
    const float cx = coord[bq * 2 + 1];
    const float s0 = scale[bq * 2 + 0];
    const float s1 = scale[bq * 2 + 1];
    const float lo = -1.0f + 1e-6f, hi = 1.0f - 1e-6f;

    int   qy[4], qx[4];
    float area[4];
    const float rx = 1.0f / 64.0f, ry = 1.0f / 64.0f;
    #pragma unroll
    for (int s = 0; s < 4; s++) {
        float vx = (s >= 2) ? 1.0f : -1.0f;
        float vy = (s & 1)  ? 1.0f : -1.0f;
        float c0 = fminf(fmaxf(cy + vx * rx + 1e-6f, lo), hi);
        float c1 = fminf(fmaxf(cx + vy * ry + 1e-6f, lo), hi);
        int iy = nearest_idx(c0), ix = nearest_idx(c1);
        qy[s] = iy; qx[s] = ix;
        float qc0 = -1.0f + (2.0f * iy + 1.0f) / 64.0f;
        float qc1 = -1.0f + (2.0f * ix + 1.0f) / 64.0f;
        area[s] = fabsf((cy - qc0) * 64.0f * (cx - qc1) * 64.0f) + 1e-9f;
    }
    float tot = area[0] + area[1] + area[2] + area[3];
    float qw[4];
    #pragma unroll
    for (int s = 0; s < 4; s++) qw[s] = area[3 - s] / tot;

    const float sc00 = scale[(b * QQ) * 2 + 0];
    const float sc01 = scale[(b * QQ) * 2 + 1];
    const float invtx = (1.0f - sc00) / 63.0f;
    const float invty = (1.0f - sc01) / 63.0f;
    int   ky[4], kx[4];
    float kr0[4], kr1[4];
    #pragma unroll
    for (int s = 0; s < 4; s++) {
        float vx = (s >= 2) ? 1.0f : -1.0f;
        float vy = (s & 1)  ? 1.0f : -1.0f;
        float c0 = fminf(fmaxf(cy + vx * invtx + 1e-6f, lo), hi);
        float c1 = fminf(fmaxf(cx + vy * invty + 1e-6f, lo), hi);
        int iy = nearest_idx(c0), ix = nearest_idx(c1);
        ky[s] = iy; kx[s] = ix;
        float qc0 = -1.0f + (2.0f * iy + 1.0f) / 64.0f;
        float qc1 = -1.0f + (2.0f * ix + 1.0f) / 64.0f;
        kr0[s] = (cy - qc0) * 64.0f;
        kr1[s] = (cx - qc1) * 64.0f;
    }

    const float* fb = feature + (size_t)b * CC * HH * WW;
    for (int k = tid; k < CK; k += 128) {
        int c = k / 9, p = k - c * 9;
        int di = p / 3 - 1, dj = p - (p / 3) * 3 - 1;
        const float* fc = fb + (size_t)c * (HH * WW);
        float qacc = 0.f;
        #pragma unroll
        for (int s = 0; s < 4; s++) {
            int y = qy[s] + di, x = qx[s] + dj;
            float v = ((unsigned)y < 64u && (unsigned)x < 64u) ? fc[y * 64 + x] : 0.f;
            qacc += qw[s] * v;
        }
        g_QRY[(size_t)bq * CK + k] = qacc;
        #pragma unroll
        for (int s = 0; s < 4; s++) {
            int y = ky[s] + di, x = kx[s] + dj;
            float v = ((unsigned)y < 64u && (unsigned)x < 64u) ? fc[y * 64 + x] : 0.f;
            g_INPh[((size_t)(bq * 4 + s)) * KINP + k] = __float2half_rn(v);
        }
    }
    {   // cols 576..607: rel(2), scale(2), zeros. 128 thr = 4 shifts x 32 cols.
        int s = tid >> 5, cc = tid & 31;
        float v = 0.f;
        if (cc == 0) v = kr0[s];
        else if (cc == 1) v = kr1[s];
        else if (cc == 2) v = s0 * 64.0f;
        else if (cc == 3) v = s1 * 64.0f;
        g_INPh[((size_t)(bq * 4 + s)) * KINP + 576 + cc] = __float2half_rn(v);
    }
}

// ---------------- fp16 mma.sync GEMM (unguarded, dual-set) ------------------
// C[M,N] = A[M,K(lda)] @ B[N,K]^T, half in, fp32 acc, half out.
// BM=128, BN=128, BK=32, 3-stage cp.async. REQUIRES M%128==0, N%128==0, K%32==0.
// blockIdx.z picks operand set 0/1 (merged launches).
// EPI 0: half(relu(acc+bias)).  EPI 1: half((acc+bias)*mul[gm*ldmul+gn]).
#define TILEB 8192                  // bytes per operand tile
#define STAGEB 16384
#define SMEMB (3*STAGEB)            // 49152

__device__ __forceinline__ void cp16(uint32_t dst, const __half* src) {
    asm volatile("cp.async.cg.shared.global [%0], [%1], 16;" :: "r"(dst), "l"(src) : "memory");
}
#define MMA_F16(acc, a0, a1, a2, a3, b0, b1)                                     \
    asm volatile("mma.sync.aligned.m16n8k16.row.col.f32.f16.f16.f32 "            \
        "{%0,%1,%2,%3}, {%4,%5,%6,%7}, {%8,%9}, {%0,%1,%2,%3};"                  \
        : "+f"((acc)[0]), "+f"((acc)[1]), "+f"((acc)[2]), "+f"((acc)[3])         \
        : "r"(a0), "r"(a1), "r"(a2), "r"(a3), "r"(b0), "r"(b1))

template<int EPI>
__global__ __launch_bounds__(256, 2) void mma_gemm(
    const __half* __restrict__ A0, const __half* __restrict__ A1, int lda,
    const __half* __restrict__ B0, const __half* __restrict__ B1,
    __half* __restrict__ C0, __half* __restrict__ C1,
    const float* __restrict__ bias0, const float* __restrict__ bias1,
    const __half* __restrict__ mul, int ldmul, int K, int N) {
    extern __shared__ char smem[];
    const int tid = threadIdx.x;
    const int lane = tid & 31, wid = tid >> 5;
    const int g = lane >> 2, tg = lane & 3;
    const int wm = (wid & 3) * 32, wn = (wid >> 2) * 64;
    const int bm = blockIdx.y * 128, bn = blockIdx.x * 128;
    const int S = K >> 5;
    const uint32_t sbase = s2u(smem);

    const __half* A = blockIdx.z ? A1 : A0;
    const __half* B = blockIdx.z ? B1 : B0;
    __half*       C = blockIdx.z ? C1 : C0;
    const float* bias = blockIdx.z ? bias1 : bias0;

    const __half* Ab = A + (size_t)bm * lda;
    const __half* Bb = B + (size_t)bn * K;

    float acc[2][8][4];
    #pragma unroll
    for (int mt = 0; mt < 2; mt++)
        #pragma unroll
        for (int nt = 0; nt < 8; nt++)
            #pragma unroll
            for (int j = 0; j < 4; j++) acc[mt][nt][j] = 0.f;

    auto issue = [&](int st, int k0) {
        uint32_t aB = sbase + (uint32_t)(st * STAGEB);
        uint32_t bB = aB + TILEB;
        #pragma unroll
        for (int r = 0; r < 2; r++) {
            int c = tid + r * 256;          // 512 chunks of 16B per tile
            int row = c >> 2, q = c & 3;    // 4 x 16B per 64B row
            cp16(aB + (uint32_t)(row * 64 + q * 16), Ab + (size_t)row * lda + k0 + q * 8);
            cp16(bB + (uint32_t)(row * 64 + q * 16), Bb + (size_t)row * K + k0 + q * 8);
        }
        asm volatile("cp.async.commit_group;" ::: "memory");
    };

    issue(0, 0);
    issue(1, 32);

    for (int s = 0; s < S; s++) {
        asm volatile("cp.async.wait_group 1;" ::: "memory");
        __syncthreads();

        if (s + 2 < S) issue((s + 2) % 3, (s + 2) * 32);

        const __half* As = (const __half*)(smem + (s % 3) * STAGEB);
        const __half* Bs = As + TILEB / 2;

        uint4 a0[2], a1[2];
        #pragma unroll
        for (int mt = 0; mt < 2; mt++) {
            int m0 = wm + mt * 16 + g;
            a0[mt] = *(const uint4*)(As + m0 * 32 + 8 * tg);
            a1[mt] = *(const uint4*)(As + (m0 + 8) * 32 + 8 * tg);
        }
        #pragma unroll
        for (int nt = 0; nt < 8; nt++) {
            int n0 = wn + nt * 8 + g;
            uint4 bv = *(const uint4*)(Bs + n0 * 32 + 8 * tg);
            #pragma unroll
            for (int mt = 0; mt < 2; mt++) {
                MMA_F16(acc[mt][nt], a0[mt].x, a1[mt].x, a0[mt].y, a1[mt].y, bv.x, bv.y);
                MMA_F16(acc[mt][nt], a0[mt].z, a1[mt].z, a0[mt].w, a1[mt].w, bv.z, bv.w);
            }
        }
        __syncthreads();
    }

    // epilogue: c0,c1 -> row g cols 2tg,2tg+1; c2,c3 -> row g+8
    #pragma unroll
    for (int mt = 0; mt < 2; mt++) {
        int gm0 = bm + wm + mt * 16 + g;
        #pragma unroll
        for (int nt = 0; nt < 8; nt++) {
            int gn = bn + wn + nt * 8 + 2 * tg;
            float b0 = bias[gn], b1 = bias[gn + 1];
            float v0 = acc[mt][nt][0] + b0;
            float v1 = acc[mt][nt][1] + b1;
            float v2 = acc[mt][nt][2] + b0;
            float v3 = acc[mt][nt][3] + b1;
            if (EPI == 0) {
                v0 = fmaxf(v0, 0.f); v1 = fmaxf(v1, 0.f);
                v2 = fmaxf(v2, 0.f); v3 = fmaxf(v3, 0.f);
            } else {
                float2 m0v = __half22float2(*(const __half2*)(mul + (size_t)gm0 * ldmul + gn));
                float2 m1v = __half22float2(*(const __half2*)(mul + (size_t)(gm0 + 8) * ldmul + gn));
                v0 *= m0v.x; v1 *= m0v.y; v2 *= m1v.x; v3 *= m1v.y;
            }
            *(__half2*)(C + (size_t)gm0 * N + gn) = __floats2half2_rn(v0, v1);
            *(__half2*)(C + (size_t)(gm0 + 8) * N + gn) = __floats2half2_rn(v2, v3);
        }
    }
}

// ---------------- attention: dot, softmax(4), weighted sum -----------------
__global__ __launch_bounds__(192) void attn_kernel() {
    const int bq = blockIdx.x;
    const int tid = threadIdx.x;
    const float4* q4 = (const float4*)(g_QRY + (size_t)bq * CK);
    const __half* pk = g_PKh + (size_t)bq * 4 * CKP;
    const __half* pv = g_PVh + (size_t)bq * 4 * CKP;

    float p[4] = {0.f, 0.f, 0.f, 0.f};
    if (tid < 144) {                       // CK/4 = 144, 4 halves per thread
        float4 q = q4[tid];
        #pragma unroll
        for (int s = 0; s < 4; s++) {
            uint2 u = *(const uint2*)(pk + (size_t)s * CKP + tid * 4);
            float2 f0 = __half22float2(*(__half2*)&u.x);
            float2 f1 = __half22float2(*(__half2*)&u.y);
            p[s] = q.x * f0.x + q.y * f0.y + q.z * f1.x + q.w * f1.y;
        }
    }
    #pragma unroll
    for (int off = 16; off; off >>= 1)
        #pragma unroll
        for (int s = 0; s < 4; s++)
            p[s] += __shfl_down_sync(0xffffffffu, p[s], off);

    __shared__ float red[4][6];
    __shared__ float wsm[4];
    int warp = tid >> 5, lane = tid & 31;
    if (lane == 0)
        #pragma unroll
        for (int s = 0; s < 4; s++) red[s][warp] = p[s];
    __syncthreads();
    if (tid == 0) {
        float attn[4];
        #pragma unroll
        for (int s = 0; s < 4; s++)
            attn[s] = red[s][0] + red[s][1] + red[s][2] + red[s][3] + red[s][4] + red[s][5];
        float m = fmaxf(fmaxf(attn[0], attn[1]), fmaxf(attn[2], attn[3]));
        float e[4], t = 0.f;
        #pragma unroll
        for (int s = 0; s < 4; s++) { e[s] = expf(attn[s] - m); t += e[s]; }
        float inv = 1.0f / t;
        #pragma unroll
        for (int s = 0; s < 4; s++) wsm[s] = e[s] * inv;
    }
    __syncthreads();
    if (tid < 144) {
        float x0 = 0.f, x1 = 0.f, x2 = 0.f, x3 = 0.f;
        #pragma unroll
        for (int s = 0; s < 4; s++) {
            float w = wsm[s];
            uint2 u = *(const uint2*)(pv + (size_t)s * CKP + tid * 4);
            float2 f0 = __half22float2(*(__half2*)&u.x);
            float2 f1 = __half22float2(*(__half2*)&u.y);
            x0 += w * f0.x; x1 += w * f0.y; x2 += w * f1.x; x3 += w * f1.y;
        }
        __half2* xp = (__half2*)(g_Xh + (size_t)bq * CK);
        xp[tid * 2 + 0] = __floats2half2_rn(x0, x1);
        xp[tid * 2 + 1] = __floats2half2_rn(x2, x3);
    }
}

// ---------------- final projection: [8192,256] @ [256,3] + bias ------------
__global__ __launch_bounds__(128) void outproj_kernel(
    const float* __restrict__ qW2, const float* __restrict__ qb2,
    float* __restrict__ out) {
    int warp = threadIdx.x >> 5, lane = threadIdx.x & 31;
    int row = blockIdx.x * 4 + warp;
    const __half* h = g_Hqh + (size_t)row * HID;
    float a0 = 0.f, a1 = 0.f, a2 = 0.f;
    #pragma unroll
    for (int i = 0; i < 8; i++) {
        int k = i * 32 + lane;
        float a = __half2float(h[k]);
        a0 += a * qW2[k * 3 + 0];
        a1 += a * qW2[k * 3 + 1];
        a2 += a * qW2[k * 3 + 2];
    }
    #pragma unroll
    for (int off = 16; off; off >>= 1) {
        a0 += __shfl_down_sync(0xffffffffu, a0, off);
        a1 += __shfl_down_sync(0xffffffffu, a1, off);
        a2 += __shfl_down_sync(0xffffffffu, a2, off);
    }
    if (lane == 0) {
        out[row * 3 + 0] = a0 + qb2[0];
        out[row * 3 + 1] = a1 + qb2[1];
        out[row * 3 + 2] = a2 + qb2[2];
    }
}

// ---------------- launch ---------------------------------------------------
extern "C" void kernel_launch(void* const* d_in, const int* in_sizes, int n_in,
                              void* d_out, int out_size) {
    const float* feature = (const float*)d_in[0];
    const float* coord   = (const float*)d_in[1];
    const float* scale   = (const float*)d_in[2];
    const float* kW1 = (const float*)d_in[3];
    const float* kb1 = (const float*)d_in[4];
    const float* kW2 = (const float*)d_in[5];
    const float* kb2 = (const float*)d_in[6];
    const float* vW1 = (const float*)d_in[7];
    const float* vb1 = (const float*)d_in[8];
    const float* vW2 = (const float*)d_in[9];
    const float* vb2 = (const float*)d_in[10];
    const float* qW1 = (const float*)d_in[11];
    const float* qb1 = (const float*)d_in[12];
    const float* qW2 = (const float*)d_in[13];
    const float* qb2 = (const float*)d_in[14];
    float* out = (float*)d_out;

    __half *pINP, *pH, *pPK, *pPV, *pX, *pHq, *pW1t, *pkW2t, *pvW2t, *pqW1t;
    float *pb1, *pkb2p, *pvb2p;
    cudaGetSymbolAddress((void**)&pINP,  g_INPh);
    cudaGetSymbolAddress((void**)&pH,    g_Hh);
    cudaGetSymbolAddress((void**)&pPK,   g_PKh);
    cudaGetSymbolAddress((void**)&pPV,   g_PVh);
    cudaGetSymbolAddress((void**)&pX,    g_Xh);
    cudaGetSymbolAddress((void**)&pHq,   g_Hqh);
    cudaGetSymbolAddress((void**)&pW1t,  g_W1t);
    cudaGetSymbolAddress((void**)&pb1,   g_b1);
    cudaGetSymbolAddress((void**)&pkW2t, g_kW2t);
    cudaGetSymbolAddress((void**)&pvW2t, g_vW2t);
    cudaGetSymbolAddress((void**)&pkb2p, g_kb2p);
    cudaGetSymbolAddress((void**)&pvb2p, g_vb2p);
    cudaGetSymbolAddress((void**)&pqW1t, g_qW1t);

    cudaFuncSetAttribute(mma_gemm<0>, cudaFuncAttributeMaxDynamicSharedMemorySize, SMEMB);
    cudaFuncSetAttribute(mma_gemm<1>, cudaFuncAttributeMaxDynamicSharedMemorySize, SMEMB);

    // 0) transpose/pad weights -> fp16
    prep_weights<<<(512 * KINP + 255) / 256, 256>>>(kW1, vW1, kW2, vW2, qW1,
                                                    kb1, vb1, kb2, vb2);

    // 1) gather/setup
    setup_kernel<<<NROW, 128>>>(feature, coord, scale);

    // 2) fused layer-1:  H[:, 0:512] = relu(INP @ W1t^T + b1), K=608, N=512
    {
        dim3 grid(4, NROW4 / 128, 1);
        mma_gemm<0><<<grid, 256, SMEMB>>>(pINP, pINP, KINP, pW1t, pW1t, pH, pH,
                                          pb1, pb1, nullptr, 0, KINP, 512);
    }

    // 3) layer-2 MLPs (merged):  P = kv * (H @ W2t^T + b2), K=256, N=640, z=k/v
    {
        dim3 grid(CKP / 128, NROW4 / 128, 2);
        mma_gemm<1><<<grid, 256, SMEMB>>>(pH, pH + 256, 512, pkW2t, pvW2t,
                                          pPK, pPV, pkb2p, pvb2p,
                                          pINP, KINP, HID, CKP);
    }

    // 4) attention + softmax + weighted sum -> X     [8192 x 576]
    attn_kernel<<<NROW, 192>>>();

    // 5) query MLP layer 1: Hq = relu(X @ qW1t^T + qb1), K=576, N=256
    {
        dim3 grid(2, NROW / 128, 1);
        mma_gemm<0><<<grid, 256, SMEMB>>>(pX, pX, CK, pqW1t, pqW1t, pHq, pHq,
                                          qb1, qb1, nullptr, 0, CK, HID);
    }

    // 6) output projection  [8192 x 3]
    outproj_kernel<<<NROW / 4, 128>>>(qW2, qb2, out);
}

// round 9
// speedup vs baseline: 1.6880x; 1.0542x over previous
#include <cuda_runtime.h>
#include <cuda_fp16.h>
#include <math.h>
#include <stdint.h>

// Problem constants
#define BB 2
#define QQ 4096
#define CC 64
#define HH 64
#define WW 64
#define CK 576          // C*9
#define KIN 580         // CK + 4
#define KINP 608        // K padding for layer-1 (mult of 32)
#define CKP 640         // N padding for layer-2 (mult of 128)
#define HID 256
#define NROW (BB*QQ)        // 8192
#define NROW4 (BB*QQ*4)     // 32768

// ---------------- scratch (device globals; no allocation) ----------------
__device__ __half g_INPh[NROW4 * KINP + 64];  // [32768, 608] (+64 pad: unguarded epi-mul read)
__device__ float  g_QRYp[NROW * CKP];         // [8192, 640] fp32, cols 576.. zero
__device__ __half g_Hh  [NROW4 * 512];        // cols 0..255 Hk, 256..511 Hv
__device__ __half g_PVh [NROW4 * CKP];        // stride 640
__device__ float  g_attn[NROW4];              // fused dot accumulators
__device__ float  g_W   [NROW4];              // softmax weights (4 per bq)
__device__ __half g_Xh  [NROW * CK];
__device__ __half g_Hqh [NROW * HID];
// weights, [N, K] K-major, fp16
__device__ __half g_W1t [512 * KINP];         // kW1t rows 0..255, vW1t rows 256..511
__device__ float  g_b1  [512];
__device__ __half g_kW2t[CKP * HID];          // rows 576..639 zero
__device__ __half g_vW2t[CKP * HID];
__device__ float  g_kb2p[CKP];                // padded biases
__device__ float  g_vb2p[CKP];
__device__ __half g_qW1t[HID * CK];

__device__ __forceinline__ uint32_t s2u(const void* p) {
    uint32_t a;
    asm("{ .reg .u64 t; cvta.to.shared.u64 t, %1; cvt.u32.u64 %0, t; }" : "=r"(a) : "l"(p));
    return a;
}

// ---------------- weight transpose / pad / fp16 ----------------------------
__global__ void prep_weights(const float* __restrict__ kW1, const float* __restrict__ vW1,
                             const float* __restrict__ kW2, const float* __restrict__ vW2,
                             const float* __restrict__ qW1,
                             const float* __restrict__ kb1, const float* __restrict__ vb1,
                             const float* __restrict__ kb2, const float* __restrict__ vb2) {
    int i = blockIdx.x * 256 + threadIdx.x;
    if (i < 512 * KINP) {           // fused W1: [512, 608]
        int n = i / KINP, k = i - n * KINP;
        float v = 0.f;
        if (k < KIN) v = (n < HID) ? kW1[k * HID + n] : vW1[k * HID + (n - HID)];
        g_W1t[i] = __float2half_rn(v);
    }
    if (i < CKP * HID) {            // [640, 256] from [256, 576], zero rows >= 576
        int n = i / HID, k = i - n * HID;
        float a = 0.f, b = 0.f;
        if (n < CK) { a = kW2[k * CK + n]; b = vW2[k * CK + n]; }
        g_kW2t[i] = __float2half_rn(a);
        g_vW2t[i] = __float2half_rn(b);
    }
    if (i < HID * CK) {             // [256, 576] from [576, 256]
        int n = i / CK, k = i - n * CK;
        g_qW1t[i] = __float2half_rn(qW1[k * HID + n]);
    }
    if (i < 512)
        g_b1[i] = (i < HID) ? kb1[i] : vb1[i - HID];
    if (i < CKP) {
        g_kb2p[i] = (i < CK) ? kb2[i] : 0.f;
        g_vb2p[i] = (i < CK) ? vb2[i] : 0.f;
    }
}

// ---------------- setup: gather unfold samples, build INP + query ----------
__device__ __forceinline__ int nearest_idx(float c) {
    float f = ((c + 1.0f) * 64.0f - 1.0f) * 0.5f + 0.5f;
    int i = (int)floorf(f);
    return i < 0 ? 0 : (i > 63 ? 63 : i);
}

__global__ __launch_bounds__(128) void setup_kernel(
    const float* __restrict__ feature, const float* __restrict__ coord,
    const float* __restrict__ scale) {
    const int bq = blockIdx.x;
    const int b  = bq >> 12;
    const int tid = threadIdx.x;

    const float cy = coord[bq * 2 + 0];
    const float cx = coord[bq * 2 + 1];
    const float s0 = scale[bq * 2 + 0];
    const float s1 = scale[bq * 2 + 1];
    const float lo = -1.0f + 1e-6f, hi = 1.0f - 1e-6f;

    int   qy[4], qx[4];
    float area[4];
    const float rx = 1.0f / 64.0f, ry = 1.0f / 64.0f;
    #pragma unroll
    for (int s = 0; s < 4; s++) {
        float vx = (s >= 2) ? 1.0f : -1.0f;
        float vy = (s & 1)  ? 1.0f : -1.0f;
        float c0 = fminf(fmaxf(cy + vx * rx + 1e-6f, lo), hi);
        float c1 = fminf(fmaxf(cx + vy * ry + 1e-6f, lo), hi);
        int iy = nearest_idx(c0), ix = nearest_idx(c1);
        qy[s] = iy; qx[s] = ix;
        float qc0 = -1.0f + (2.0f * iy + 1.0f) / 64.0f;
        float qc1 = -1.0f + (2.0f * ix + 1.0f) / 64.0f;
        area[s] = fabsf((cy - qc0) * 64.0f * (cx - qc1) * 64.0f) + 1e-9f;
    }
    float tot = area[0] + area[1] + area[2] + area[3];
    float qw[4];
    #pragma unroll
    for (int s = 0; s < 4; s++) qw[s] = area[3 - s] / tot;

    const float sc00 = scale[(b * QQ) * 2 + 0];
    const float sc01 = scale[(b * QQ) * 2 + 1];
    const float invtx = (1.0f - sc00) / 63.0f;
    const float invty = (1.0f - sc01) / 63.0f;
    int   ky[4], kx[4];
    float kr0[4], kr1[4];
    #pragma unroll
    for (int s = 0; s < 4; s++) {
        float vx = (s >= 2) ? 1.0f : -1.0f;
        float vy = (s & 1)  ? 1.0f : -1.0f;
        float c0 = fminf(fmaxf(cy + vx * invtx + 1e-6f, lo), hi);
        float c1 = fminf(fmaxf(cx + vy * invty + 1e-6f, lo), hi);
        int iy = nearest_idx(c0), ix = nearest_idx(c1);
        ky[s] = iy; kx[s] = ix;
        float qc0 = -1.0f + (2.0f * iy + 1.0f) / 64.0f;
        float qc1 = -1.0f + (2.0f * ix + 1.0f) / 64.0f;
        kr0[s] = (cy - qc0) * 64.0f;
        kr1[s] = (cx - qc1) * 64.0f;
    }

    const float* fb = feature + (size_t)b * CC * HH * WW;
    for (int k = tid; k < CK; k += 128) {
        int c = k / 9, p = k - c * 9;
        int di = p / 3 - 1, dj = p - (p / 3) * 3 - 1;
        const float* fc = fb + (size_t)c * (HH * WW);
        float qacc = 0.f;
        #pragma unroll
        for (int s = 0; s < 4; s++) {
            int y = qy[s] + di, x = qx[s] + dj;
            float v = ((unsigned)y < 64u && (unsigned)x < 64u) ? fc[y * 64 + x] : 0.f;
            qacc += qw[s] * v;
        }
        g_QRYp[(size_t)bq * CKP + k] = qacc;
        #pragma unroll
        for (int s = 0; s < 4; s++) {
            int y = ky[s] + di, x = kx[s] + dj;
            float v = ((unsigned)y < 64u && (unsigned)x < 64u) ? fc[y * 64 + x] : 0.f;
            g_INPh[((size_t)(bq * 4 + s)) * KINP + k] = __float2half_rn(v);
        }
    }
    if (tid < 64)        // zero query pad cols 576..639
        g_QRYp[(size_t)bq * CKP + CK + tid] = 0.f;
    if (tid < 4)         // zero attn accumulators (re-zeroed every launch)
        g_attn[bq * 4 + tid] = 0.f;
    {   // cols 576..607: rel(2), scale(2), zeros. 128 thr = 4 shifts x 32 cols.
        int s = tid >> 5, cc = tid & 31;
        float v = 0.f;
        if (cc == 0) v = kr0[s];
        else if (cc == 1) v = kr1[s];
        else if (cc == 2) v = s0 * 64.0f;
        else if (cc == 3) v = s1 * 64.0f;
        g_INPh[((size_t)(bq * 4 + s)) * KINP + 576 + cc] = __float2half_rn(v);
    }
}

// ---------------- fp16 mma.sync GEMM (unguarded, dual-set) ------------------
// C[M,N] = A[M,K(lda)] @ B[N,K]^T, half in, fp32 acc.
// BM=128, BN=128, BK=32, 3-stage cp.async. REQUIRES M%128==0, N%128==0, K%32==0.
// blockIdx.z picks operand set 0/1.
// EPI 0: half(relu(acc+bias)) -> C.
// EPI 2: layer-2 fused. z=0 (k): dot((acc+bias)*mul, query) -> atomicAdd g_attn,
//        no store. z=1 (v): half((acc+bias)*mul) -> C.
#define TILEB 8192                  // bytes per operand tile
#define STAGEB 16384
#define SMEMB (3*STAGEB)            // 49152

__device__ __forceinline__ void cp16(uint32_t dst, const __half* src) {
    asm volatile("cp.async.cg.shared.global [%0], [%1], 16;" :: "r"(dst), "l"(src) : "memory");
}
#define MMA_F16(acc, a0, a1, a2, a3, b0, b1)                                     \
    asm volatile("mma.sync.aligned.m16n8k16.row.col.f32.f16.f16.f32 "            \
        "{%0,%1,%2,%3}, {%4,%5,%6,%7}, {%8,%9}, {%0,%1,%2,%3};"                  \
        : "+f"((acc)[0]), "+f"((acc)[1]), "+f"((acc)[2]), "+f"((acc)[3])         \
        : "r"(a0), "r"(a1), "r"(a2), "r"(a3), "r"(b0), "r"(b1))

template<int EPI>
__global__ __launch_bounds__(256, 2) void mma_gemm(
    const __half* __restrict__ A0, const __half* __restrict__ A1, int lda,
    const __half* __restrict__ B0, const __half* __restrict__ B1,
    __half* __restrict__ C0, __half* __restrict__ C1,
    const float* __restrict__ bias0, const float* __restrict__ bias1,
    const __half* __restrict__ mul, int ldmul, int K, int N) {
    extern __shared__ char smem[];
    const int tid = threadIdx.x;
    const int lane = tid & 31, wid = tid >> 5;
    const int g = lane >> 2, tg = lane & 3;
    const int wm = (wid & 3) * 32, wn = (wid >> 2) * 64;
    const int bm = blockIdx.y * 128, bn = blockIdx.x * 128;
    const int S = K >> 5;
    const uint32_t sbase = s2u(smem);

    const __half* A = blockIdx.z ? A1 : A0;
    const __half* B = blockIdx.z ? B1 : B0;
    __half*       C = blockIdx.z ? C1 : C0;
    const float* bias = blockIdx.z ? bias1 : bias0;

    const __half* Ab = A + (size_t)bm * lda;
    const __half* Bb = B + (size_t)bn * K;

    float acc[2][8][4];
    #pragma unroll
    for (int mt = 0; mt < 2; mt++)
        #pragma unroll
        for (int nt = 0; nt < 8; nt++)
            #pragma unroll
            for (int j = 0; j < 4; j++) acc[mt][nt][j] = 0.f;

    auto issue = [&](int st, int k0) {
        uint32_t aB = sbase + (uint32_t)(st * STAGEB);
        uint32_t bB = aB + TILEB;
        #pragma unroll
        for (int r = 0; r < 2; r++) {
            int c = tid + r * 256;          // 512 chunks of 16B per tile
            int row = c >> 2, q = c & 3;    // 4 x 16B per 64B row
            cp16(aB + (uint32_t)(row * 64 + q * 16), Ab + (size_t)row * lda + k0 + q * 8);
            cp16(bB + (uint32_t)(row * 64 + q * 16), Bb + (size_t)row * K + k0 + q * 8);
        }
        asm volatile("cp.async.commit_group;" ::: "memory");
    };

    issue(0, 0);
    issue(1, 32);

    for (int s = 0; s < S; s++) {
        asm volatile("cp.async.wait_group 1;" ::: "memory");
        __syncthreads();

        if (s + 2 < S) issue((s + 2) % 3, (s + 2) * 32);

        const __half* As = (const __half*)(smem + (s % 3) * STAGEB);
        const __half* Bs = As + TILEB / 2;

        uint4 a0[2], a1[2];
        #pragma unroll
        for (int mt = 0; mt < 2; mt++) {
            int m0 = wm + mt * 16 + g;
            a0[mt] = *(const uint4*)(As + m0 * 32 + 8 * tg);
            a1[mt] = *(const uint4*)(As + (m0 + 8) * 32 + 8 * tg);
        }
        #pragma unroll
        for (int nt = 0; nt < 8; nt++) {
            int n0 = wn + nt * 8 + g;
            uint4 bv = *(const uint4*)(Bs + n0 * 32 + 8 * tg);
            #pragma unroll
            for (int mt = 0; mt < 2; mt++) {
                MMA_F16(acc[mt][nt], a0[mt].x, a1[mt].x, a0[mt].y, a1[mt].y, bv.x, bv.y);
                MMA_F16(acc[mt][nt], a0[mt].z, a1[mt].z, a0[mt].w, a1[mt].w, bv.z, bv.w);
            }
        }
        __syncthreads();
    }

    // epilogue: c0,c1 -> row g cols 2tg,2tg+1; c2,c3 -> row g+8
    if (EPI == 0 || blockIdx.z == 1) {
        #pragma unroll
        for (int mt = 0; mt < 2; mt++) {
            int gm0 = bm + wm + mt * 16 + g;
            #pragma unroll
            for (int nt = 0; nt < 8; nt++) {
                int gn = bn + wn + nt * 8 + 2 * tg;
                float b0 = bias[gn], b1 = bias[gn + 1];
                float v0 = acc[mt][nt][0] + b0;
                float v1 = acc[mt][nt][1] + b1;
                float v2 = acc[mt][nt][2] + b0;
                float v3 = acc[mt][nt][3] + b1;
                if (EPI == 0) {
                    v0 = fmaxf(v0, 0.f); v1 = fmaxf(v1, 0.f);
                    v2 = fmaxf(v2, 0.f); v3 = fmaxf(v3, 0.f);
                } else {
                    float2 m0v = __half22float2(*(const __half2*)(mul + (size_t)gm0 * ldmul + gn));
                    float2 m1v = __half22float2(*(const __half2*)(mul + (size_t)(gm0 + 8) * ldmul + gn));
                    v0 *= m0v.x; v1 *= m0v.y; v2 *= m1v.x; v3 *= m1v.y;
                }
                *(__half2*)(C + (size_t)gm0 * N + gn) = __floats2half2_rn(v0, v1);
                *(__half2*)(C + (size_t)(gm0 + 8) * N + gn) = __floats2half2_rn(v2, v3);
            }
        }
    } else {
        // EPI==2, z==0 (k-side): fused attention dot, no store
        #pragma unroll
        for (int mt = 0; mt < 2; mt++) {
            int gm0 = bm + wm + mt * 16 + g;
            const float* q0 = g_QRYp + (size_t)(gm0 >> 2) * CKP;
            const float* q1 = g_QRYp + (size_t)((gm0 + 8) >> 2) * CKP;
            float dot0 = 0.f, dot1 = 0.f;
            #pragma unroll
            for (int nt = 0; nt < 8; nt++) {
                int gn = bn + wn + nt * 8 + 2 * tg;
                float b0 = bias[gn], b1 = bias[gn + 1];
                float2 m0v = __half22float2(*(const __half2*)(mul + (size_t)gm0 * ldmul + gn));
                float2 m1v = __half22float2(*(const __half2*)(mul + (size_t)(gm0 + 8) * ldmul + gn));
                float v0 = (acc[mt][nt][0] + b0) * m0v.x;
                float v1 = (acc[mt][nt][1] + b1) * m0v.y;
                float v2 = (acc[mt][nt][2] + b0) * m1v.x;
                float v3 = (acc[mt][nt][3] + b1) * m1v.y;
                float2 qa = *(const float2*)(q0 + gn);
                float2 qb = *(const float2*)(q1 + gn);
                dot0 += v0 * qa.x + v1 * qa.y;
                dot1 += v2 * qb.x + v3 * qb.y;
            }
            dot0 += __shfl_xor_sync(0xffffffffu, dot0, 1);
            dot0 += __shfl_xor_sync(0xffffffffu, dot0, 2);
            dot1 += __shfl_xor_sync(0xffffffffu, dot1, 1);
            dot1 += __shfl_xor_sync(0xffffffffu, dot1, 2);
            if (tg == 0) {
                atomicAdd(&g_attn[gm0], dot0);
                atomicAdd(&g_attn[gm0 + 8], dot1);
            }
        }
    }
}

// ---------------- softmax over the 4 shifts --------------------------------
__global__ __launch_bounds__(256) void softmax_kernel() {
    int bq = blockIdx.x * 256 + threadIdx.x;     // 8192 threads
    float4 a = *(const float4*)&g_attn[bq * 4];
    float m = fmaxf(fmaxf(a.x, a.y), fmaxf(a.z, a.w));
    float e0 = expf(a.x - m), e1 = expf(a.y - m), e2 = expf(a.z - m), e3 = expf(a.w - m);
    float inv = 1.0f / (e0 + e1 + e2 + e3);
    float4 w = {e0 * inv, e1 * inv, e2 * inv, e3 * inv};
    *(float4*)&g_W[bq * 4] = w;
}

// ---------------- weighted PV sum -> X -------------------------------------
__global__ __launch_bounds__(160) void attnw_kernel() {
    const int bq = blockIdx.x;
    const int tid = threadIdx.x;
    if (tid < 144) {                       // CK/4 = 144, 4 halves per thread
        float4 w = *(const float4*)&g_W[bq * 4];
        const __half* pv = g_PVh + (size_t)bq * 4 * CKP;
        float x0 = 0.f, x1 = 0.f, x2 = 0.f, x3 = 0.f;
        float ws[4] = {w.x, w.y, w.z, w.w};
        #pragma unroll
        for (int s = 0; s < 4; s++) {
            uint2 u = *(const uint2*)(pv + (size_t)s * CKP + tid * 4);
            float2 f0 = __half22float2(*(__half2*)&u.x);
            float2 f1 = __half22float2(*(__half2*)&u.y);
            x0 += ws[s] * f0.x; x1 += ws[s] * f0.y;
            x2 += ws[s] * f1.x; x3 += ws[s] * f1.y;
        }
        __half2* xp = (__half2*)(g_Xh + (size_t)bq * CK);
        xp[tid * 2 + 0] = __floats2half2_rn(x0, x1);
        xp[tid * 2 + 1] = __floats2half2_rn(x2, x3);
    }
}

// ---------------- final projection: [8192,256] @ [256,3] + bias ------------
__global__ __launch_bounds__(128) void outproj_kernel(
    const float* __restrict__ qW2, const float* __restrict__ qb2,
    float* __restrict__ out) {
    int warp = threadIdx.x >> 5, lane = threadIdx.x & 31;
    int row = blockIdx.x * 4 + warp;
    const __half* h = g_Hqh + (size_t)row * HID;
    float a0 = 0.f, a1 = 0.f, a2 = 0.f;
    #pragma unroll
    for (int i = 0; i < 8; i++) {
        int k = i * 32 + lane;
        float a = __half2float(h[k]);
        a0 += a * qW2[k * 3 + 0];
        a1 += a * qW2[k * 3 + 1];
        a2 += a * qW2[k * 3 + 2];
    }
    #pragma unroll
    for (int off = 16; off; off >>= 1) {
        a0 += __shfl_down_sync(0xffffffffu, a0, off);
        a1 += __shfl_down_sync(0xffffffffu, a1, off);
        a2 += __shfl_down_sync(0xffffffffu, a2, off);
    }
    if (lane == 0) {
        out[row * 3 + 0] = a0 + qb2[0];
        out[row * 3 + 1] = a1 + qb2[1];
        out[row * 3 + 2] = a2 + qb2[2];
    }
}

// ---------------- launch ---------------------------------------------------
extern "C" void kernel_launch(void* const* d_in, const int* in_sizes, int n_in,
                              void* d_out, int out_size) {
    const float* feature = (const float*)d_in[0];
    const float* coord   = (const float*)d_in[1];
    const float* scale   = (const float*)d_in[2];
    const float* kW1 = (const float*)d_in[3];
    const float* kb1 = (const float*)d_in[4];
    const float* kW2 = (const float*)d_in[5];
    const float* kb2 = (const float*)d_in[6];
    const float* vW1 = (const float*)d_in[7];
    const float* vb1 = (const float*)d_in[8];
    const float* vW2 = (const float*)d_in[9];
    const float* vb2 = (const float*)d_in[10];
    const float* qW1 = (const float*)d_in[11];
    const float* qb1 = (const float*)d_in[12];
    const float* qW2 = (const float*)d_in[13];
    const float* qb2 = (const float*)d_in[14];
    float* out = (float*)d_out;

    __half *pINP, *pH, *pPV, *pX, *pHq, *pW1t, *pkW2t, *pvW2t, *pqW1t;
    float *pb1, *pkb2p, *pvb2p;
    cudaGetSymbolAddress((void**)&pINP,  g_INPh);
    cudaGetSymbolAddress((void**)&pH,    g_Hh);
    cudaGetSymbolAddress((void**)&pPV,   g_PVh);
    cudaGetSymbolAddress((void**)&pX,    g_Xh);
    cudaGetSymbolAddress((void**)&pHq,   g_Hqh);
    cudaGetSymbolAddress((void**)&pW1t,  g_W1t);
    cudaGetSymbolAddress((void**)&pb1,   g_b1);
    cudaGetSymbolAddress((void**)&pkW2t, g_kW2t);
    cudaGetSymbolAddress((void**)&pvW2t, g_vW2t);
    cudaGetSymbolAddress((void**)&pkb2p, g_kb2p);
    cudaGetSymbolAddress((void**)&pvb2p, g_vb2p);
    cudaGetSymbolAddress((void**)&pqW1t, g_qW1t);

    cudaFuncSetAttribute(mma_gemm<0>, cudaFuncAttributeMaxDynamicSharedMemorySize, SMEMB);
    cudaFuncSetAttribute(mma_gemm<2>, cudaFuncAttributeMaxDynamicSharedMemorySize, SMEMB);

    // 0) transpose/pad weights -> fp16
    prep_weights<<<(512 * KINP + 255) / 256, 256>>>(kW1, vW1, kW2, vW2, qW1,
                                                    kb1, vb1, kb2, vb2);

    // 1) gather/setup (also zeros g_attn + query pad)
    setup_kernel<<<NROW, 128>>>(feature, coord, scale);

    // 2) fused layer-1:  H[:, 0:512] = relu(INP @ W1t^T + b1), K=608, N=512
    {
        dim3 grid(4, NROW4 / 128, 1);
        mma_gemm<0><<<grid, 256, SMEMB>>>(pINP, pINP, KINP, pW1t, pW1t, pH, pH,
                                          pb1, pb1, nullptr, 0, KINP, 512);
    }

    // 3) layer-2 merged: z=0 k-side (fused dot -> g_attn, no store),
    //                    z=1 v-side (PV store). K=256, N=640.
    {
        dim3 grid(CKP / 128, NROW4 / 128, 2);
        mma_gemm<2><<<grid, 256, SMEMB>>>(pH, pH + 256, 512, pkW2t, pvW2t,
                                          pPV, pPV, pkb2p, pvb2p,
                                          pINP, KINP, HID, CKP);
    }

    // 4) softmax over shifts, then weighted PV sum -> X
    softmax_kernel<<<NROW / 256, 256>>>();
    attnw_kernel<<<NROW, 160>>>();

    // 5) query MLP layer 1: Hq = relu(X @ qW1t^T + qb1), K=576, N=256
    {
        dim3 grid(2, NROW / 128, 1);
        mma_gemm<0><<<grid, 256, SMEMB>>>(pX, pX, CK, pqW1t, pqW1t, pHq, pHq,
                                          qb1, qb1, nullptr, 0, CK, HID);
    }

    // 6) output projection  [8192 x 3]
    outproj_kernel<<<NROW / 4, 128>>>(qW2, qb2, out);
}

// round 11
// speedup vs baseline: 1.9390x; 1.1487x over previous
#include <cuda_runtime.h>
#include <cuda_fp16.h>
#include <math.h>
#include <stdint.h>

// Problem constants
#define BB 2
#define QQ 4096
#define CC 64
#define HH 64
#define WW 64
#define CK 576          // C*9
#define KIN 580         // CK + 4
#define KINP 608        // K padding for layer-1 (mult of 32)
#define CKP 640         // N padding for layer-2 (mult of 128)
#define HID 256
#define NROW (BB*QQ)        // 8192
#define NROW4 (BB*QQ*4)     // 32768

// ---------------- scratch (device globals; no allocation) ----------------
__device__ __half g_INPh[NROW4 * KINP + 64];  // [32768, 608] (+64 pad: unguarded epi-mul read)
__device__ float  g_QRYp[NROW * CKP];         // [8192, 640] fp32, cols 576.. zero
__device__ __half g_Hh  [NROW4 * 512];        // cols 0..255 Hk, 256..511 Hv
__device__ __half g_PVh [NROW4 * CKP];        // stride 640
__device__ float  g_attn[NROW4];              // fused dot accumulators
__device__ float  g_W   [NROW4];              // softmax weights (4 per bq)
__device__ __half g_Xh  [NROW * CK];
__device__ __half g_Hqh [NROW * HID];
// weights, [N, K] K-major, fp16
__device__ __half g_W1t [512 * KINP];         // kW1t rows 0..255, vW1t rows 256..511
__device__ float  g_b1  [512];
__device__ __half g_kW2t[CKP * HID];          // rows 576..639 zero
__device__ __half g_vW2t[CKP * HID];
__device__ float  g_kb2p[CKP];                // padded biases
__device__ float  g_vb2p[CKP];
__device__ __half g_qW1t[HID * CK];

__device__ __forceinline__ uint32_t s2u(const void* p) {
    uint32_t a;
    asm("{ .reg .u64 t; cvta.to.shared.u64 t, %1; cvt.u32.u64 %0, t; }" : "=r"(a) : "l"(p));
    return a;
}

// ---------------- weight transpose / pad / fp16 ----------------------------
__global__ void prep_weights(const float* __restrict__ kW1, const float* __restrict__ vW1,
                             const float* __restrict__ kW2, const float* __restrict__ vW2,
                             const float* __restrict__ qW1,
                             const float* __restrict__ kb1, const float* __restrict__ vb1,
                             const float* __restrict__ kb2, const float* __restrict__ vb2) {
    int i = blockIdx.x * 256 + threadIdx.x;
    if (i < 512 * KINP) {           // fused W1: [512, 608]
        int n = i / KINP, k = i - n * KINP;
        float v = 0.f;
        if (k < KIN) v = (n < HID) ? kW1[k * HID + n] : vW1[k * HID + (n - HID)];
        g_W1t[i] = __float2half_rn(v);
    }
    if (i < CKP * HID) {            // [640, 256] from [256, 576], zero rows >= 576
        int n = i / HID, k = i - n * HID;
        float a = 0.f, b = 0.f;
        if (n < CK) { a = kW2[k * CK + n]; b = vW2[k * CK + n]; }
        g_kW2t[i] = __float2half_rn(a);
        g_vW2t[i] = __float2half_rn(b);
    }
    if (i < HID * CK) {             // [256, 576] from [576, 256]
        int n = i / CK, k = i - n * CK;
        g_qW1t[i] = __float2half_rn(qW1[k * HID + n]);
    }
    if (i < 512)
        g_b1[i] = (i < HID) ? kb1[i] : vb1[i - HID];
    if (i < CKP) {
        g_kb2p[i] = (i < CK) ? kb2[i] : 0.f;
        g_vb2p[i] = (i < CK) ? vb2[i] : 0.f;
    }
}

// ---------------- setup: gather unfold samples, build INP + query ----------
__device__ __forceinline__ int nearest_idx(float c) {
    float f = ((c + 1.0f) * 64.0f - 1.0f) * 0.5f + 0.5f;
    int i = (int)floorf(f);
    return i < 0 ? 0 : (i > 63 ? 63 : i);
}

__global__ __launch_bounds__(128) void setup_kernel(
    const float* __restrict__ feature, const float* __restrict__ coord,
    const float* __restrict__ scale) {
    const int bq = blockIdx.x;
    const int b  = bq >> 12;
    const int tid = threadIdx.x;

    const float cy = coord[bq * 2 + 0];
    const float cx = coord[bq * 2 + 1];
    const float s0 = scale[bq * 2 + 0];
    const float s1 = scale[bq * 2 + 1];
    const float lo = -1.0f + 1e-6f, hi = 1.0f - 1e-6f;

    int   qy[4], qx[4];
    float area[4];
    const float rx = 1.0f / 64.0f, ry = 1.0f / 64.0f;
    #pragma unroll
    for (int s = 0; s < 4; s++) {
        float vx = (s >= 2) ? 1.0f : -1.0f;
        float vy = (s & 1)  ? 1.0f : -1.0f;
        float c0 = fminf(fmaxf(cy + vx * rx + 1e-6f, lo), hi);
        float c1 = fminf(fmaxf(cx + vy * ry + 1e-6f, lo), hi);
        int iy = nearest_idx(c0), ix = nearest_idx(c1);
        qy[s] = iy; qx[s] = ix;
        float qc0 = -1.0f + (2.0f * iy + 1.0f) / 64.0f;
        float qc1 = -1.0f + (2.0f * ix + 1.0f) / 64.0f;
        area[s] = fabsf((cy - qc0) * 64.0f * (cx - qc1) * 64.0f) + 1e-9f;
    }
    float tot = area[0] + area[1] + area[2] + area[3];
    float qw[4];
    #pragma unroll
    for (int s = 0; s < 4; s++) qw[s] = area[3 - s] / tot;

    const float sc00 = scale[(b * QQ) * 2 + 0];
    const float sc01 = scale[(b * QQ) * 2 + 1];
    const float invtx = (1.0f - sc00) / 63.0f;
    const float invty = (1.0f - sc01) / 63.0f;
    int   ky[4], kx[4];
    float kr0[4], kr1[4];
    #pragma unroll
    for (int s = 0; s < 4; s++) {
        float vx = (s >= 2) ? 1.0f : -1.0f;
        float vy = (s & 1)  ? 1.0f : -1.0f;
        float c0 = fminf(fmaxf(cy + vx * invtx + 1e-6f, lo), hi);
        float c1 = fminf(fmaxf(cx + vy * invty + 1e-6f, lo), hi);
        int iy = nearest_idx(c0), ix = nearest_idx(c1);
        ky[s] = iy; kx[s] = ix;
        float qc0 = -1.0f + (2.0f * iy + 1.0f) / 64.0f;
        float qc1 = -1.0f + (2.0f * ix + 1.0f) / 64.0f;
        kr0[s] = (cy - qc0) * 64.0f;
        kr1[s] = (cx - qc1) * 64.0f;
    }

    const float* fb = feature + (size_t)b * CC * HH * WW;
    for (int k = tid; k < CK; k += 128) {
        int c = k / 9, p = k - c * 9;
        int di = p / 3 - 1, dj = p - (p / 3) * 3 - 1;
        const float* fc = fb + (size_t)c * (HH * WW);
        float qacc = 0.f;
        #pragma unroll
        for (int s = 0; s < 4; s++) {
            int y = qy[s] + di, x = qx[s] + dj;
            float v = ((unsigned)y < 64u && (unsigned)x < 64u) ? fc[y * 64 + x] : 0.f;
            qacc += qw[s] * v;
        }
        g_QRYp[(size_t)bq * CKP + k] = qacc;
        #pragma unroll
        for (int s = 0; s < 4; s++) {
            int y = ky[s] + di, x = kx[s] + dj;
            float v = ((unsigned)y < 64u && (unsigned)x < 64u) ? fc[y * 64 + x] : 0.f;
            g_INPh[((size_t)(bq * 4 + s)) * KINP + k] = __float2half_rn(v);
        }
    }
    if (tid < 64)        // zero query pad cols 576..639
        g_QRYp[(size_t)bq * CKP + CK + tid] = 0.f;
    if (tid < 4)         // zero attn accumulators (re-zeroed every launch)
        g_attn[bq * 4 + tid] = 0.f;
    {   // cols 576..607: rel(2), scale(2), zeros. 128 thr = 4 shifts x 32 cols.
        int s = tid >> 5, cc = tid & 31;
        float v = 0.f;
        if (cc == 0) v = kr0[s];
        else if (cc == 1) v = kr1[s];
        else if (cc == 2) v = s0 * 64.0f;
        else if (cc == 3) v = s1 * 64.0f;
        g_INPh[((size_t)(bq * 4 + s)) * KINP + 576 + cc] = __float2half_rn(v);
    }
}

// ---------------- fp16 mma.sync GEMM (compile-time K, unguarded) ------------
// C[M,N] = A[M,K(lda)] @ B[N,K]^T, half in, fp32 acc.  K = 32*S (template).
// BM=128, BN=128, BK=32, 3-stage cp.async, stage loop FULLY UNROLLED.
// blockIdx.z picks operand set 0/1.
// EPI 0: half(relu(acc+bias)) -> C.
// EPI 2: z=0 (k): dot((acc+bias)*mul, query) -> atomicAdd g_attn, no store.
//        z=1 (v): half((acc+bias)*mul) -> C.
#define TILEB 8192                  // bytes per operand tile
#define STAGEB 16384
#define SMEMB (3*STAGEB)            // 49152

__device__ __forceinline__ void cp16(uint32_t dst, const __half* src) {
    asm volatile("cp.async.cg.shared.global [%0], [%1], 16;" :: "r"(dst), "l"(src) : "memory");
}
#define MMA_F16(acc, a0, a1, a2, a3, b0, b1)                                     \
    asm volatile("mma.sync.aligned.m16n8k16.row.col.f32.f16.f16.f32 "            \
        "{%0,%1,%2,%3}, {%4,%5,%6,%7}, {%8,%9}, {%0,%1,%2,%3};"                  \
        : "+f"((acc)[0]), "+f"((acc)[1]), "+f"((acc)[2]), "+f"((acc)[3])         \
        : "r"(a0), "r"(a1), "r"(a2), "r"(a3), "r"(b0), "r"(b1))

template<int EPI, int S>
__global__ __launch_bounds__(256, 2) void mma_gemm(
    const __half* __restrict__ A0, const __half* __restrict__ A1, int lda,
    const __half* __restrict__ B0, const __half* __restrict__ B1,
    __half* __restrict__ C0, __half* __restrict__ C1,
    const float* __restrict__ bias0, const float* __restrict__ bias1,
    const __half* __restrict__ mul, int ldmul, int N) {
    extern __shared__ char smem[];
    constexpr int K = 32 * S;
    const int tid = threadIdx.x;
    const int lane = tid & 31, wid = tid >> 5;
    const int g = lane >> 2, tg = lane & 3;
    const int wm = (wid & 3) * 32, wn = (wid >> 2) * 64;
    const int bm = blockIdx.y * 128, bn = blockIdx.x * 128;
    const uint32_t sbase = s2u(smem);

    const __half* A = blockIdx.z ? A1 : A0;
    const __half* B = blockIdx.z ? B1 : B0;
    __half*       C = blockIdx.z ? C1 : C0;
    const float* bias = blockIdx.z ? bias1 : bias0;

    // per-thread fixed load coordinates (hoisted once)
    const int ldrow = tid >> 2, ldq = tid & 3;             // rows 0..63 (+64 second chunk)
    const __half* gA0 = A + (size_t)(bm + ldrow) * lda + ldq * 8;
    const __half* gA1 = A + (size_t)(bm + ldrow + 64) * lda + ldq * 8;
    const __half* gB0 = B + (size_t)(bn + ldrow) * K + ldq * 8;
    const __half* gB1 = B + (size_t)(bn + ldrow + 64) * K + ldq * 8;
    const uint32_t sAo = (uint32_t)(ldrow * 64 + ldq * 16);
    const uint32_t sBo = sAo + TILEB;
    const uint32_t sA1o = sAo + 64 * 64;
    const uint32_t sB1o = sBo + 64 * 64;

    float acc[2][8][4];
    #pragma unroll
    for (int mt = 0; mt < 2; mt++)
        #pragma unroll
        for (int nt = 0; nt < 8; nt++)
            #pragma unroll
            for (int j = 0; j < 4; j++) acc[mt][nt][j] = 0.f;

    // smem fragment offsets (halves), hoisted
    const uint32_t fa0 = (uint32_t)((wm + g) * 32 + 8 * tg);
    const uint32_t fb0 = (uint32_t)((wn + g) * 32 + 8 * tg);

    #pragma unroll
    for (int p = 0; p < 2; p++) {          // prologue stages 0,1
        uint32_t st = sbase + p * STAGEB;
        cp16(st + sAo,  gA0 + p * 32);
        cp16(st + sA1o, gA1 + p * 32);
        cp16(st + sBo,  gB0 + p * 32);
        cp16(st + sB1o, gB1 + p * 32);
        asm volatile("cp.async.commit_group;" ::: "memory");
    }

    #pragma unroll
    for (int s = 0; s < S; s++) {
        asm volatile("cp.async.wait_group 1;" ::: "memory");
        __syncthreads();

        if (s + 2 < S) {
            uint32_t st = sbase + ((s + 2) % 3) * STAGEB;   // compile-time folded
            cp16(st + sAo,  gA0 + (s + 2) * 32);
            cp16(st + sA1o, gA1 + (s + 2) * 32);
            cp16(st + sBo,  gB0 + (s + 2) * 32);
            cp16(st + sB1o, gB1 + (s + 2) * 32);
            asm volatile("cp.async.commit_group;" ::: "memory");
        }

        const __half* As = (const __half*)(smem + (s % 3) * STAGEB);
        const __half* Bs = As + TILEB / 2;

        uint4 a0[2], a1[2];
        #pragma unroll
        for (int mt = 0; mt < 2; mt++) {
            a0[mt] = *(const uint4*)(As + fa0 + mt * 16 * 32);
            a1[mt] = *(const uint4*)(As + fa0 + mt * 16 * 32 + 8 * 32);
        }
        #pragma unroll
        for (int nt = 0; nt < 8; nt++) {
            uint4 bv = *(const uint4*)(Bs + fb0 + nt * 8 * 32);
            #pragma unroll
            for (int mt = 0; mt < 2; mt++) {
                MMA_F16(acc[mt][nt], a0[mt].x, a1[mt].x, a0[mt].y, a1[mt].y, bv.x, bv.y);
                MMA_F16(acc[mt][nt], a0[mt].z, a1[mt].z, a0[mt].w, a1[mt].w, bv.z, bv.w);
            }
        }
        __syncthreads();
    }

    // epilogue: c0,c1 -> row g cols 2tg,2tg+1; c2,c3 -> row g+8
    if (EPI == 0 || blockIdx.z == 1) {
        #pragma unroll
        for (int mt = 0; mt < 2; mt++) {
            int gm0 = bm + wm + mt * 16 + g;
            #pragma unroll
            for (int nt = 0; nt < 8; nt++) {
                int gn = bn + wn + nt * 8 + 2 * tg;
                float b0 = bias[gn], b1 = bias[gn + 1];
                float v0 = acc[mt][nt][0] + b0;
                float v1 = acc[mt][nt][1] + b1;
                float v2 = acc[mt][nt][2] + b0;
                float v3 = acc[mt][nt][3] + b1;
                if (EPI == 0) {
                    v0 = fmaxf(v0, 0.f); v1 = fmaxf(v1, 0.f);
                    v2 = fmaxf(v2, 0.f); v3 = fmaxf(v3, 0.f);
                } else {
                    float2 m0v = __half22float2(*(const __half2*)(mul + (size_t)gm0 * ldmul + gn));
                    float2 m1v = __half22float2(*(const __half2*)(mul + (size_t)(gm0 + 8) * ldmul + gn));
                    v0 *= m0v.x; v1 *= m0v.y; v2 *= m1v.x; v3 *= m1v.y;
                }
                *(__half2*)(C + (size_t)gm0 * N + gn) = __floats2half2_rn(v0, v1);
                *(__half2*)(C + (size_t)(gm0 + 8) * N + gn) = __floats2half2_rn(v2, v3);
            }
        }
    } else {
        // EPI==2, z==0 (k-side): fused attention dot, no store
        #pragma unroll
        for (int mt = 0; mt < 2; mt++) {
            int gm0 = bm + wm + mt * 16 + g;
            const float* q0 = g_QRYp + (size_t)(gm0 >> 2) * CKP;
            const float* q1 = g_QRYp + (size_t)((gm0 + 8) >> 2) * CKP;
            float dot0 = 0.f, dot1 = 0.f;
            #pragma unroll
            for (int nt = 0; nt < 8; nt++) {
                int gn = bn + wn + nt * 8 + 2 * tg;
                float b0 = bias[gn], b1 = bias[gn + 1];
                float2 m0v = __half22float2(*(const __half2*)(mul + (size_t)gm0 * ldmul + gn));
                float2 m1v = __half22float2(*(const __half2*)(mul + (size_t)(gm0 + 8) * ldmul + gn));
                float v0 = (acc[mt][nt][0] + b0) * m0v.x;
                float v1 = (acc[mt][nt][1] + b1) * m0v.y;
                float v2 = (acc[mt][nt][2] + b0) * m1v.x;
                float v3 = (acc[mt][nt][3] + b1) * m1v.y;
                float2 qa = *(const float2*)(q0 + gn);
                float2 qb = *(const float2*)(q1 + gn);
                dot0 += v0 * qa.x + v1 * qa.y;
                dot1 += v2 * qb.x + v3 * qb.y;
            }
            dot0 += __shfl_xor_sync(0xffffffffu, dot0, 1);
            dot0 += __shfl_xor_sync(0xffffffffu, dot0, 2);
            dot1 += __shfl_xor_sync(0xffffffffu, dot1, 1);
            dot1 += __shfl_xor_sync(0xffffffffu, dot1, 2);
            if (tg == 0) {
                atomicAdd(&g_attn[gm0], dot0);
                atomicAdd(&g_attn[gm0 + 8], dot1);
            }
        }
    }
}

// ---------------- softmax over the 4 shifts --------------------------------
__global__ __launch_bounds__(256) void softmax_kernel() {
    int bq = blockIdx.x * 256 + threadIdx.x;     // 8192 threads
    float4 a = *(const float4*)&g_attn[bq * 4];
    float m = fmaxf(fmaxf(a.x, a.y), fmaxf(a.z, a.w));
    float e0 = expf(a.x - m), e1 = expf(a.y - m), e2 = expf(a.z - m), e3 = expf(a.w - m);
    float inv = 1.0f / (e0 + e1 + e2 + e3);
    float4 w = {e0 * inv, e1 * inv, e2 * inv, e3 * inv};
    *(float4*)&g_W[bq * 4] = w;
}

// ---------------- weighted PV sum -> X -------------------------------------
__global__ __launch_bounds__(160) void attnw_kernel() {
    const int bq = blockIdx.x;
    const int tid = threadIdx.x;
    if (tid < 144) {                       // CK/4 = 144, 4 halves per thread
        float4 w = *(const float4*)&g_W[bq * 4];
        const __half* pv = g_PVh + (size_t)bq * 4 * CKP;
        float x0 = 0.f, x1 = 0.f, x2 = 0.f, x3 = 0.f;
        float ws[4] = {w.x, w.y, w.z, w.w};
        #pragma unroll
        for (int s = 0; s < 4; s++) {
            uint2 u = *(const uint2*)(pv + (size_t)s * CKP + tid * 4);
            float2 f0 = __half22float2(*(__half2*)&u.x);
            float2 f1 = __half22float2(*(__half2*)&u.y);
            x0 += ws[s] * f0.x; x1 += ws[s] * f0.y;
            x2 += ws[s] * f1.x; x3 += ws[s] * f1.y;
        }
        __half2* xp = (__half2*)(g_Xh + (size_t)bq * CK);
        xp[tid * 2 + 0] = __floats2half2_rn(x0, x1);
        xp[tid * 2 + 1] = __floats2half2_rn(x2, x3);
    }
}

// ---------------- final projection: [8192,256] @ [256,3] + bias ------------
__global__ __launch_bounds__(128) void outproj_kernel(
    const float* __restrict__ qW2, const float* __restrict__ qb2,
    float* __restrict__ out) {
    int warp = threadIdx.x >> 5, lane = threadIdx.x & 31;
    int row = blockIdx.x * 4 + warp;
    const __half* h = g_Hqh + (size_t)row * HID;
    float a0 = 0.f, a1 = 0.f, a2 = 0.f;
    #pragma unroll
    for (int i = 0; i < 8; i++) {
        int k = i * 32 + lane;
        float a = __half2float(h[k]);
        a0 += a * qW2[k * 3 + 0];
        a1 += a * qW2[k * 3 + 1];
        a2 += a * qW2[k * 3 + 2];
    }
    #pragma unroll
    for (int off = 16; off; off >>= 1) {
        a0 += __shfl_down_sync(0xffffffffu, a0, off);
        a1 += __shfl_down_sync(0xffffffffu, a1, off);
        a2 += __shfl_down_sync(0xffffffffu, a2, off);
    }
    if (lane == 0) {
        out[row * 3 + 0] = a0 + qb2[0];
        out[row * 3 + 1] = a1 + qb2[1];
        out[row * 3 + 2] = a2 + qb2[2];
    }
}

// ---------------- launch ---------------------------------------------------
extern "C" void kernel_launch(void* const* d_in, const int* in_sizes, int n_in,
                              void* d_out, int out_size) {
    const float* feature = (const float*)d_in[0];
    const float* coord   = (const float*)d_in[1];
    const float* scale   = (const float*)d_in[2];
    const float* kW1 = (const float*)d_in[3];
    const float* kb1 = (const float*)d_in[4];
    const float* kW2 = (const float*)d_in[5];
    const float* kb2 = (const float*)d_in[6];
    const float* vW1 = (const float*)d_in[7];
    const float* vb1 = (const float*)d_in[8];
    const float* vW2 = (const float*)d_in[9];
    const float* vb2 = (const float*)d_in[10];
    const float* qW1 = (const float*)d_in[11];
    const float* qb1 = (const float*)d_in[12];
    const float* qW2 = (const float*)d_in[13];
    const float* qb2 = (const float*)d_in[14];
    float* out = (float*)d_out;

    __half *pINP, *pH, *pPV, *pX, *pHq, *pW1t, *pkW2t, *pvW2t, *pqW1t;
    float *pb1, *pkb2p, *pvb2p;
    cudaGetSymbolAddress((void**)&pINP,  g_INPh);
    cudaGetSymbolAddress((void**)&pH,    g_Hh);
    cudaGetSymbolAddress((void**)&pPV,   g_PVh);
    cudaGetSymbolAddress((void**)&pX,    g_Xh);
    cudaGetSymbolAddress((void**)&pHq,   g_Hqh);
    cudaGetSymbolAddress((void**)&pW1t,  g_W1t);
    cudaGetSymbolAddress((void**)&pb1,   g_b1);
    cudaGetSymbolAddress((void**)&pkW2t, g_kW2t);
    cudaGetSymbolAddress((void**)&pvW2t, g_vW2t);
    cudaGetSymbolAddress((void**)&pkb2p, g_kb2p);
    cudaGetSymbolAddress((void**)&pvb2p, g_vb2p);
    cudaGetSymbolAddress((void**)&pqW1t, g_qW1t);

    cudaFuncSetAttribute(mma_gemm<0, 19>, cudaFuncAttributeMaxDynamicSharedMemorySize, SMEMB);
    cudaFuncSetAttribute(mma_gemm<2, 8>,  cudaFuncAttributeMaxDynamicSharedMemorySize, SMEMB);
    cudaFuncSetAttribute(mma_gemm<0, 18>, cudaFuncAttributeMaxDynamicSharedMemorySize, SMEMB);

    // 0) transpose/pad weights -> fp16
    prep_weights<<<(512 * KINP + 255) / 256, 256>>>(kW1, vW1, kW2, vW2, qW1,
                                                    kb1, vb1, kb2, vb2);

    // 1) gather/setup (also zeros g_attn + query pad)
    setup_kernel<<<NROW, 128>>>(feature, coord, scale);

    // 2) fused layer-1:  H[:, 0:512] = relu(INP @ W1t^T + b1), K=608, N=512
    {
        dim3 grid(4, NROW4 / 128, 1);
        mma_gemm<0, 19><<<grid, 256, SMEMB>>>(pINP, pINP, KINP, pW1t, pW1t, pH, pH,
                                              pb1, pb1, nullptr, 0, 512);
    }

    // 3) layer-2 merged: z=0 k-side (fused dot -> g_attn, no store),
    //                    z=1 v-side (PV store). K=256, N=640.
    {
        dim3 grid(CKP / 128, NROW4 / 128, 2);
        mma_gemm<2, 8><<<grid, 256, SMEMB>>>(pH, pH + 256, 512, pkW2t, pvW2t,
                                             pPV, pPV, pkb2p, pvb2p,
                                             pINP, KINP, CKP);
    }

    // 4) softmax over shifts, then weighted PV sum -> X
    softmax_kernel<<<NROW / 256, 256>>>();
    attnw_kernel<<<NROW, 160>>>();

    // 5) query MLP layer 1: Hq = relu(X @ qW1t^T + qb1), K=576, N=256
    {
        dim3 grid(2, NROW / 128, 1);
        mma_gemm<0, 18><<<grid, 256, SMEMB>>>(pX, pX, CK, pqW1t, pqW1t, pHq, pHq,
                                              qb1, qb1, nullptr, 0, 256);
    }

    // 6) output projection  [8192 x 3]
    outproj_kernel<<<NROW / 4, 128>>>(qW2, qb2, out);
}